// round 10
// baseline (speedup 1.0000x reference)
#include <cuda_runtime.h>
#include <math.h>

#define EPSBN 1e-5f

typedef unsigned long long u64;

// ---------------- device scratch (no allocations allowed) ----------------
__device__ float g_h1[64 * 32 * 112 * 112];   // 102.8 MB
__device__ float g_h2[64 * 64 * 112 * 112];   // 205.5 MB
__device__ float g_h3[64 * 128 * 56 * 56];    // 102.8 MB
__device__ float g_pool[64 * 128];
__device__ float g_qwl[10 * 128];
__device__ float g_w1r[9 * 3 * 32];           // [tap][ic][oc]
__device__ float g_w2r[9 * 32 * 64];
__device__ float g_w3r[9 * 64 * 128];

// ---------------- packed fp32x2 helpers (sm_103a) ----------------
__device__ __forceinline__ u64 pack2(float x) {
    u64 d; unsigned u = __float_as_uint(x);
    asm("mov.b64 %0, {%1, %1};" : "=l"(d) : "r"(u));
    return d;
}
__device__ __forceinline__ void fma2(u64& d, u64 a, u64 b) {
    asm("fma.rn.f32x2 %0, %1, %2, %0;" : "+l"(d) : "l"(a), "l"(b));
}
__device__ __forceinline__ float lo2(u64 v) { return __uint_as_float((unsigned)v); }
__device__ __forceinline__ float hi2(u64 v) { return __uint_as_float((unsigned)(v >> 32)); }

// ---------------- fused ternarize (TWN) + repack OIHW -> [tap][ic][oc] ----------------
// delta = 0.7*mean|w|; alpha = mean|w| over entries above delta; q = alpha*sign(w)*mask
__global__ __launch_bounds__(1024) void prep_kernel(const float* __restrict__ w,
                                                    int n, int IC, int OC, int which) {
    __shared__ double reda[1024];
    __shared__ double redc[1024];
    __shared__ float s_delta, s_alpha;
    int tid = threadIdx.x;

    double s = 0.0;
    for (int i = tid; i < n; i += 1024) s += (double)fabsf(w[i]);
    reda[tid] = s; __syncthreads();
    for (int off = 512; off > 0; off >>= 1) {
        if (tid < off) reda[tid] += reda[tid + off];
        __syncthreads();
    }
    if (tid == 0) s_delta = (float)(0.7 * reda[0] / (double)n);
    __syncthreads();
    float delta = s_delta;

    double sa = 0.0, cnt = 0.0;
    for (int i = tid; i < n; i += 1024) {
        float a = fabsf(w[i]);
        if (a > delta) { sa += (double)a; cnt += 1.0; }
    }
    reda[tid] = sa; redc[tid] = cnt; __syncthreads();
    for (int off = 512; off > 0; off >>= 1) {
        if (tid < off) { reda[tid] += reda[tid + off]; redc[tid] += redc[tid + off]; }
        __syncthreads();
    }
    if (tid == 0) s_alpha = (float)(reda[0] / fmax(redc[0], 1.0));
    __syncthreads();
    float alpha = s_alpha;

    float* out = (which == 0) ? g_w1r : (which == 1) ? g_w2r
               : (which == 2) ? g_w3r : g_qwl;
    for (int i = tid; i < n; i += 1024) {
        float wv = w[i];
        float qv = (fabsf(wv) > delta) ? copysignf(alpha, wv) : 0.0f;
        if (which < 3) {
            int r = i % 9; int t = i / 9; int ic = t % IC; int oc = t / IC;
            out[(r * IC + ic) * OC + oc] = qv;
        } else {
            out[i] = qv;
        }
    }
}

// ---------------- conv1: [64,3,224,224] -> [64,32,112,112], s2 p1, BN+ReLU ----------------
__global__ __launch_bounds__(256) void conv1_kernel(
    const float* __restrict__ x, const float* __restrict__ g, const float* __restrict__ b,
    const float* __restrict__ m, const float* __restrict__ v) {
    __shared__ __align__(16) float sX[3 * 33 * 33];
    __shared__ __align__(16) float sW[9 * 3 * 32];
    __shared__ float sBNi[32], sBNa[32];

    int tid = threadIdx.x;
    int n = blockIdx.z;
    int ty0 = blockIdx.y * 16, tx0 = blockIdx.x * 16;
    int iy0 = 2 * ty0 - 1, ix0 = 2 * tx0 - 1;

    for (int i = tid; i < 3 * 33 * 33; i += 256) {
        int lx = i % 33; int t = i / 33; int ly = t % 33; int ic = t / 33;
        int gy = iy0 + ly, gx = ix0 + lx;
        float val = 0.f;
        if (gy >= 0 && gy < 224 && gx >= 0 && gx < 224)
            val = x[((n * 3 + ic) * 224 + gy) * 224 + gx];
        sX[i] = val;
    }
    for (int i = tid; i < 9 * 3 * 32; i += 256) sW[i] = g_w1r[i];
    if (tid < 32) {
        float inv = g[tid] / sqrtf(v[tid] + EPSBN);
        sBNi[tid] = inv; sBNa[tid] = b[tid] - m[tid] * inv;
    }
    __syncthreads();

    int py = tid / 16, px = tid % 16;
    float acc[32];
#pragma unroll
    for (int k = 0; k < 32; ++k) acc[k] = 0.f;

    for (int ic = 0; ic < 3; ++ic) {
#pragma unroll
        for (int r = 0; r < 9; ++r) {
            float xv = sX[ic * 1089 + (2 * py + r / 3) * 33 + (2 * px + r % 3)];
            const float4* w4 = (const float4*)&sW[(r * 3 + ic) * 32];
#pragma unroll
            for (int j = 0; j < 8; ++j) {
                float4 w = w4[j];
                acc[4 * j + 0] += xv * w.x;
                acc[4 * j + 1] += xv * w.y;
                acc[4 * j + 2] += xv * w.z;
                acc[4 * j + 3] += xv * w.w;
            }
        }
    }

    int oy = ty0 + py, ox = tx0 + px;
    int base = (n * 32) * 12544 + oy * 112 + ox;
#pragma unroll
    for (int oc = 0; oc < 32; ++oc) {
        float val = fmaxf(acc[oc] * sBNi[oc] + sBNa[oc], 0.f);
        g_h1[base + oc * 12544] = val;
    }
}

// ---------------- conv2: [64,32,112,112] -> [64,64,112,112], s1 p1, BN+ReLU ----------------
// 448 threads; tile 16x28 output pixels. Thread = 2 pixels (py, py+8) x 32 ocs.
// Per inner iter: 2 x-LDS + 8 weight LDS.128 (warp-uniform broadcast) feed 32 FFMA2.
__global__ __launch_bounds__(448) void conv2_kernel(
    const float* __restrict__ g, const float* __restrict__ b,
    const float* __restrict__ m, const float* __restrict__ v) {
    extern __shared__ __align__(16) float smem[];
    float* sX = smem;              // 32*18*30 = 17280 floats
    float* sW = smem + 17280;      // 9*32*64  = 18432 floats
    __shared__ float sBNi[64], sBNa[64];

    int tid = threadIdx.x;
    int n = blockIdx.z;
    int ty0 = blockIdx.y * 16, tx0 = blockIdx.x * 28;

    for (int i = tid; i < 17280; i += 448) {
        int lx = i % 30; int t = i / 30; int ly = t % 18; int ic = t / 18;
        int gy = ty0 - 1 + ly, gx = tx0 - 1 + lx;
        float val = 0.f;
        if (gy >= 0 && gy < 112 && gx >= 0 && gx < 112)
            val = g_h1[((n * 32 + ic) * 112 + gy) * 112 + gx];
        sX[i] = val;
    }
    for (int i = tid; i < 18432; i += 448) sW[i] = g_w2r[i];
    if (tid < 64) {
        float inv = g[tid] / sqrtf(v[tid] + EPSBN);
        sBNi[tid] = inv; sBNa[tid] = b[tid] - m[tid] * inv;
    }
    __syncthreads();

    int half = tid / 224;          // warp-aligned: 224 = 7 warps
    int p = tid % 224;
    int py = p / 28, px = p % 28;  // py 0..7; second pixel at py+8
    int ocb = half * 32;

    u64 acc0[16], acc1[16];
#pragma unroll
    for (int k = 0; k < 16; ++k) { acc0[k] = 0ull; acc1[k] = 0ull; }

    for (int ic = 0; ic < 32; ++ic) {
        const float* xb = &sX[ic * 540 + py * 30 + px];
        const float* wb = &sW[ic * 64 + ocb];
#pragma unroll
        for (int r = 0; r < 9; ++r) {
            int dy = r / 3, dx = r % 3;
            u64 x0 = pack2(xb[dy * 30 + dx]);
            u64 x1 = pack2(xb[(dy + 8) * 30 + dx]);
            const ulonglong2* wv = (const ulonglong2*)&wb[r * 2048];  // (r*32+ic)*64
#pragma unroll
            for (int j = 0; j < 8; ++j) {
                ulonglong2 ww = wv[j];
                fma2(acc0[2 * j + 0], x0, ww.x);
                fma2(acc0[2 * j + 1], x0, ww.y);
                fma2(acc1[2 * j + 0], x1, ww.x);
                fma2(acc1[2 * j + 1], x1, ww.y);
            }
        }
    }

    int oy = ty0 + py, ox = tx0 + px;
    long base = ((long)(n * 64 + ocb)) * 12544 + oy * 112 + ox;
#pragma unroll
    for (int k = 0; k < 16; ++k) {
        int oc0 = ocb + 2 * k;
        float i0 = sBNi[oc0], a0 = sBNa[oc0];
        float i1 = sBNi[oc0 + 1], a1 = sBNa[oc0 + 1];
        g_h2[base + (2 * k + 0) * 12544]           = fmaxf(lo2(acc0[k]) * i0 + a0, 0.f);
        g_h2[base + (2 * k + 1) * 12544]           = fmaxf(hi2(acc0[k]) * i1 + a1, 0.f);
        g_h2[base + (2 * k + 0) * 12544 + 8 * 112] = fmaxf(lo2(acc1[k]) * i0 + a0, 0.f);
        g_h2[base + (2 * k + 1) * 12544 + 8 * 112] = fmaxf(hi2(acc1[k]) * i1 + a1, 0.f);
    }
}

// ---------------- conv3: [64,64,112,112] -> [64,128,56,56], s2 p1, BN+ReLU ----------------
// 448 threads; tile 8x28 output pixels. Thread = 2 pixels (py, py+4) x 32 ocs (quarter).
// IC chunked by 16 (4 chunks), weights+x staged per chunk.
__global__ __launch_bounds__(448) void conv3_kernel(
    const float* __restrict__ g, const float* __restrict__ b,
    const float* __restrict__ m, const float* __restrict__ v) {
    extern __shared__ __align__(16) float smem[];
    float* sX = smem;              // 16*17*57 = 15504 floats
    float* sW = smem + 15504;      // 9*16*128 = 18432 floats
    __shared__ float sBNi[128], sBNa[128];

    int tid = threadIdx.x;
    int n = blockIdx.z;
    int ty0 = blockIdx.y * 8, tx0 = blockIdx.x * 28;
    int iy0 = 2 * ty0 - 1, ix0 = 2 * tx0 - 1;

    if (tid < 128) {
        float inv = g[tid] / sqrtf(v[tid] + EPSBN);
        sBNi[tid] = inv; sBNa[tid] = b[tid] - m[tid] * inv;
    }

    int q = tid / 112;             // oc quarter
    int pp = tid % 112;
    int py = pp / 28, px = pp % 28;  // py 0..3; second pixel at py+4
    int ocb = q * 32;

    u64 acc0[16], acc1[16];
#pragma unroll
    for (int k = 0; k < 16; ++k) { acc0[k] = 0ull; acc1[k] = 0ull; }

    for (int chunk = 0; chunk < 4; ++chunk) {
        __syncthreads();
        for (int i = tid; i < 15504; i += 448) {
            int lx = i % 57; int t = i / 57; int ly = t % 17; int icl = t / 17;
            int ic = chunk * 16 + icl;
            int gy = iy0 + ly, gx = ix0 + lx;
            float val = 0.f;
            if (gy >= 0 && gy < 112 && gx >= 0 && gx < 112)
                val = g_h2[((n * 64 + ic) * 112 + gy) * 112 + gx];
            sX[i] = val;
        }
        for (int i = tid; i < 18432; i += 448) {
            int oc = i % 128; int t = i / 128; int icl = t % 16; int r = t / 16;
            sW[i] = g_w3r[(r * 64 + chunk * 16 + icl) * 128 + oc];
        }
        __syncthreads();

        for (int icl = 0; icl < 16; ++icl) {
            const float* xb = &sX[icl * 969 + 2 * py * 57 + 2 * px];
            const float* wb = &sW[icl * 128 + ocb];
#pragma unroll
            for (int r = 0; r < 9; ++r) {
                int dy = r / 3, dx = r % 3;
                u64 x0 = pack2(xb[dy * 57 + dx]);
                u64 x1 = pack2(xb[(dy + 8) * 57 + dx]);   // pixel py+4 -> input +8 rows
                const ulonglong2* wv = (const ulonglong2*)&wb[r * 2048];  // (r*16+icl)*128
#pragma unroll
                for (int j = 0; j < 8; ++j) {
                    ulonglong2 ww = wv[j];
                    fma2(acc0[2 * j + 0], x0, ww.x);
                    fma2(acc0[2 * j + 1], x0, ww.y);
                    fma2(acc1[2 * j + 0], x1, ww.x);
                    fma2(acc1[2 * j + 1], x1, ww.y);
                }
            }
        }
    }

    int oy = ty0 + py, ox = tx0 + px;
    long base = ((long)(n * 128 + ocb)) * 3136 + oy * 56 + ox;
#pragma unroll
    for (int k = 0; k < 16; ++k) {
        int oc0 = ocb + 2 * k;
        float i0 = sBNi[oc0], a0 = sBNa[oc0];
        float i1 = sBNi[oc0 + 1], a1 = sBNa[oc0 + 1];
        g_h3[base + (2 * k + 0) * 3136]          = fmaxf(lo2(acc0[k]) * i0 + a0, 0.f);
        g_h3[base + (2 * k + 1) * 3136]          = fmaxf(hi2(acc0[k]) * i1 + a1, 0.f);
        g_h3[base + (2 * k + 0) * 3136 + 4 * 56] = fmaxf(lo2(acc1[k]) * i0 + a0, 0.f);
        g_h3[base + (2 * k + 1) * 3136 + 4 * 56] = fmaxf(hi2(acc1[k]) * i1 + a1, 0.f);
    }
}

// ---------------- global average pool: h3 -> pool (sum; /3136 folded into final) ----------------
__global__ void pool_kernel() {
    int c = blockIdx.x;  // n*128 + oc, 8192 blocks
    const float* src = g_h3 + (long)c * 3136;
    float s = 0.f;
    for (int i = threadIdx.x; i < 3136; i += 128) s += src[i];
    __shared__ float red[4];
#pragma unroll
    for (int o = 16; o > 0; o >>= 1) s += __shfl_xor_sync(0xffffffff, s, o);
    if ((threadIdx.x & 31) == 0) red[threadIdx.x >> 5] = s;
    __syncthreads();
    if (threadIdx.x == 0) g_pool[c] = red[0] + red[1] + red[2] + red[3];
}

// ---------------- final linear: out[n,c] = mean(h3) @ qwl.T + bl ----------------
__global__ void final_kernel(const float* __restrict__ bl, float* __restrict__ out) {
    int tid = blockIdx.x * blockDim.x + threadIdx.x;
    if (tid >= 640) return;
    int n = tid / 10, c = tid % 10;
    const float* p = g_pool + n * 128;
    const float* w = g_qwl + c * 128;
    float s = 0.f;
#pragma unroll 8
    for (int k = 0; k < 128; ++k) s += p[k] * w[k];
    out[tid] = s * (1.0f / 3136.0f) + bl[c];
}

// ---------------- launch ----------------
extern "C" void kernel_launch(void* const* d_in, const int* in_sizes, int n_in,
                              void* d_out, int out_size) {
    const float* x  = (const float*)d_in[0];
    const float* w1 = (const float*)d_in[1];
    const float* g1 = (const float*)d_in[2];
    const float* b1 = (const float*)d_in[3];
    const float* m1 = (const float*)d_in[4];
    const float* v1 = (const float*)d_in[5];
    const float* w2 = (const float*)d_in[6];
    const float* g2 = (const float*)d_in[7];
    const float* b2 = (const float*)d_in[8];
    const float* m2 = (const float*)d_in[9];
    const float* v2 = (const float*)d_in[10];
    const float* w3 = (const float*)d_in[11];
    const float* g3 = (const float*)d_in[12];
    const float* b3 = (const float*)d_in[13];
    const float* m3 = (const float*)d_in[14];
    const float* v3 = (const float*)d_in[15];
    const float* wl = (const float*)d_in[16];
    const float* bl = (const float*)d_in[17];
    float* out = (float*)d_out;

    cudaFuncSetAttribute((const void*)conv2_kernel,
                         cudaFuncAttributeMaxDynamicSharedMemorySize, 142848);
    cudaFuncSetAttribute((const void*)conv3_kernel,
                         cudaFuncAttributeMaxDynamicSharedMemorySize, 135744);

    // weight prep (4 launches -> launch index 5 == conv2 for ncu -s 5 -c 1)
    prep_kernel<<<1, 1024>>>(w1, 32 * 3 * 9, 3, 32, 0);
    prep_kernel<<<1, 1024>>>(w2, 64 * 32 * 9, 32, 64, 1);
    prep_kernel<<<1, 1024>>>(w3, 128 * 64 * 9, 64, 128, 2);
    prep_kernel<<<1, 1024>>>(wl, 10 * 128, 128, 10, 3);

    // layers
    conv1_kernel<<<dim3(7, 7, 64), 256>>>(x, g1, b1, m1, v1);
    conv2_kernel<<<dim3(4, 7, 64), 448, 142848>>>(g2, b2, m2, v2);
    conv3_kernel<<<dim3(2, 7, 64), 448, 135744>>>(g3, b3, m3, v3);
    pool_kernel<<<8192, 128>>>();
    final_kernel<<<3, 256>>>(bl, out);
}

// round 11
// speedup vs baseline: 2.2212x; 2.2212x over previous
#include <cuda_runtime.h>
#include <cuda_bf16.h>
#include <math.h>

#define EPSBN 1e-5f

// ---------------- device scratch (no allocations allowed) ----------------
// h1: NHWC [64][112][112][64ch]  ch = (icgrp*32) + (half*16) + (ic%16), half 0=hi,1=lo
__device__ __align__(16) __nv_bfloat16 g_h1[64 * 112 * 112 * 64];    // 102.8 MB
// h2: NHWC [64][112][112][128ch] same grouping (4 groups of 16 ic, hi|lo per group)
__device__ __align__(16) __nv_bfloat16 g_h2[64 * 112 * 112 * 128];   // 205.5 MB
__device__ float g_pool[64 * 128];
__device__ float g_qwl[10 * 128];
__device__ float g_w1r[9 * 3 * 32];                                  // fp32 q (alpha included)
__device__ __align__(16) __nv_bfloat16 g_w2b[9 * 32 * 72];           // ternary t, oc padded 64->72
__device__ __align__(16) __nv_bfloat16 g_w3b[9 * 64 * 136];          // ternary t, oc padded 128->136
__device__ float g_alpha[4];

// ---------------- mma / ldmatrix helpers ----------------
__device__ __forceinline__ unsigned sptr(const void* p) {
    return (unsigned)__cvta_generic_to_shared(p);
}
__device__ __forceinline__ void ldsm4(unsigned& r0, unsigned& r1, unsigned& r2, unsigned& r3, unsigned a) {
    asm volatile("ldmatrix.sync.aligned.m8n8.x4.shared.b16 {%0,%1,%2,%3},[%4];"
                 : "=r"(r0), "=r"(r1), "=r"(r2), "=r"(r3) : "r"(a));
}
__device__ __forceinline__ void ldsm4t(unsigned& r0, unsigned& r1, unsigned& r2, unsigned& r3, unsigned a) {
    asm volatile("ldmatrix.sync.aligned.m8n8.x4.trans.shared.b16 {%0,%1,%2,%3},[%4];"
                 : "=r"(r0), "=r"(r1), "=r"(r2), "=r"(r3) : "r"(a));
}
__device__ __forceinline__ void mma_bf16(float* d, unsigned a0, unsigned a1, unsigned a2, unsigned a3,
                                         unsigned b0, unsigned b1) {
    asm volatile("mma.sync.aligned.m16n8k16.row.col.f32.bf16.bf16.f32 "
                 "{%0,%1,%2,%3},{%4,%5,%6,%7},{%8,%9},{%0,%1,%2,%3};"
                 : "+f"(d[0]), "+f"(d[1]), "+f"(d[2]), "+f"(d[3])
                 : "r"(a0), "r"(a1), "r"(a2), "r"(a3), "r"(b0), "r"(b1));
}
__device__ __forceinline__ unsigned pack_bf16x2(float v0, float v1) {
    return (unsigned)__bfloat16_as_ushort(__float2bfloat16(v0)) |
           ((unsigned)__bfloat16_as_ushort(__float2bfloat16(v1)) << 16);
}

// ---------------- prep: ternarize all 4 weights in parallel (grid=4) ----------------
// delta = 0.7*mean|w|; alpha = mean|w| over entries above delta
__global__ __launch_bounds__(1024) void prep_kernel(
    const float* __restrict__ w1, const float* __restrict__ w2,
    const float* __restrict__ w3, const float* __restrict__ wl) {
    __shared__ double reda[1024];
    __shared__ double redc[1024];
    __shared__ float s_delta, s_alpha;
    int which = blockIdx.x;
    const float* w = (which == 0) ? w1 : (which == 1) ? w2 : (which == 2) ? w3 : wl;
    int n = (which == 0) ? 864 : (which == 1) ? 18432 : (which == 2) ? 73728 : 1280;
    int tid = threadIdx.x;

    double s = 0.0;
    for (int i = tid; i < n; i += 1024) s += (double)fabsf(w[i]);
    reda[tid] = s; __syncthreads();
    for (int off = 512; off > 0; off >>= 1) {
        if (tid < off) reda[tid] += reda[tid + off];
        __syncthreads();
    }
    if (tid == 0) s_delta = (float)(0.7 * reda[0] / (double)n);
    __syncthreads();
    float delta = s_delta;

    double sa = 0.0, cnt = 0.0;
    for (int i = tid; i < n; i += 1024) {
        float a = fabsf(w[i]);
        if (a > delta) { sa += (double)a; cnt += 1.0; }
    }
    reda[tid] = sa; redc[tid] = cnt; __syncthreads();
    for (int off = 512; off > 0; off >>= 1) {
        if (tid < off) { reda[tid] += reda[tid + off]; redc[tid] += redc[tid + off]; }
        __syncthreads();
    }
    if (tid == 0) s_alpha = (float)(reda[0] / fmax(redc[0], 1.0));
    __syncthreads();
    float alpha = s_alpha;
    if (tid == 0) g_alpha[which] = alpha;

    if (which == 0) {
        for (int i = tid; i < n; i += 1024) {
            float wv = w[i];
            float qv = (fabsf(wv) > delta) ? copysignf(alpha, wv) : 0.0f;
            int r = i % 9; int t = i / 9; int ic = t % 3; int oc = t / 3;
            g_w1r[(r * 3 + ic) * 32 + oc] = qv;
        }
    } else if (which == 1) {
        for (int i = tid; i < n; i += 1024) {
            float wv = w[i];
            float tv = (fabsf(wv) > delta) ? (wv > 0.f ? 1.f : -1.f) : 0.0f;
            int r = i % 9; int t = i / 9; int ic = t % 32; int oc = t / 32;
            g_w2b[(r * 32 + ic) * 72 + oc] = __float2bfloat16(tv);
        }
    } else if (which == 2) {
        for (int i = tid; i < n; i += 1024) {
            float wv = w[i];
            float tv = (fabsf(wv) > delta) ? (wv > 0.f ? 1.f : -1.f) : 0.0f;
            int r = i % 9; int t = i / 9; int ic = t % 64; int oc = t / 64;
            g_w3b[(r * 64 + ic) * 136 + oc] = __float2bfloat16(tv);
        }
    } else {
        for (int i = tid; i < n; i += 1024) {
            float wv = w[i];
            g_qwl[i] = (fabsf(wv) > delta) ? copysignf(alpha, wv) : 0.0f;
        }
        for (int i = tid; i < 64 * 128; i += 1024) g_pool[i] = 0.f;  // zero pool accum
    }
}

// ---------------- conv1: [64,3,224,224] -> h1 NHWC bf16 hi/lo, s2 p1, BN+ReLU ----------------
__global__ __launch_bounds__(256) void conv1_kernel(
    const float* __restrict__ x, const float* __restrict__ g, const float* __restrict__ b,
    const float* __restrict__ m, const float* __restrict__ v) {
    __shared__ __align__(16) float sX[3 * 33 * 33];
    __shared__ __align__(16) float sW[9 * 3 * 32];
    __shared__ float sBNi[32], sBNa[32];

    int tid = threadIdx.x;
    int n = blockIdx.z;
    int ty0 = blockIdx.y * 16, tx0 = blockIdx.x * 16;
    int iy0 = 2 * ty0 - 1, ix0 = 2 * tx0 - 1;

    for (int i = tid; i < 3 * 33 * 33; i += 256) {
        int lx = i % 33; int t = i / 33; int ly = t % 33; int ic = t / 33;
        int gy = iy0 + ly, gx = ix0 + lx;
        float val = 0.f;
        if (gy >= 0 && gy < 224 && gx >= 0 && gx < 224)
            val = x[((n * 3 + ic) * 224 + gy) * 224 + gx];
        sX[i] = val;
    }
    for (int i = tid; i < 9 * 3 * 32; i += 256) sW[i] = g_w1r[i];
    if (tid < 32) {
        float inv = g[tid] / sqrtf(v[tid] + EPSBN);
        sBNi[tid] = inv; sBNa[tid] = b[tid] - m[tid] * inv;
    }
    __syncthreads();

    int py = tid / 16, px = tid % 16;
    float acc[32];
#pragma unroll
    for (int k = 0; k < 32; ++k) acc[k] = 0.f;

    for (int ic = 0; ic < 3; ++ic) {
#pragma unroll
        for (int r = 0; r < 9; ++r) {
            float xv = sX[ic * 1089 + (2 * py + r / 3) * 33 + (2 * px + r % 3)];
            const float4* w4 = (const float4*)&sW[(r * 3 + ic) * 32];
#pragma unroll
            for (int j = 0; j < 8; ++j) {
                float4 w = w4[j];
                acc[4 * j + 0] += xv * w.x;
                acc[4 * j + 1] += xv * w.y;
                acc[4 * j + 2] += xv * w.z;
                acc[4 * j + 3] += xv * w.w;
            }
        }
    }

    int oy = ty0 + py, ox = tx0 + px;
    long pix = ((long)(n * 112 + oy)) * 112 + ox;
    unsigned short buf[64];
#pragma unroll
    for (int oc = 0; oc < 32; ++oc) {
        float val = fmaxf(acc[oc] * sBNi[oc] + sBNa[oc], 0.f);
        __nv_bfloat16 h = __float2bfloat16(val);
        __nv_bfloat16 l = __float2bfloat16(val - __bfloat162float(h));
        int chh = ((oc >> 4) << 5) + (oc & 15);
        buf[chh] = __bfloat16_as_ushort(h);
        buf[chh + 16] = __bfloat16_as_ushort(l);
    }
    uint4* dst = (uint4*)(g_h1 + pix * 64);
    const uint4* srcb = (const uint4*)buf;
#pragma unroll
    for (int j = 0; j < 8; ++j) dst[j] = srcb[j];
}

// ---------------- conv2 (tensor core): h1 -> h2, 3x3 s1 p1, BN+ReLU ----------------
// Block: 8x16 out pixels (M=128), N=64 ocs, 256 thr (8 warps: 4 m-groups x 2 n-groups).
// K per tap = 64 (32 hi + 32 lo interleaved per 16-ic group). Warp tile 32px x 32oc.
__global__ __launch_bounds__(256) void conv2_mma(
    const float* __restrict__ g, const float* __restrict__ b,
    const float* __restrict__ m, const float* __restrict__ v) {
    extern __shared__ __align__(16) char smem[];
    __nv_bfloat16* sX = (__nv_bfloat16*)smem;              // 180 rows x 72 ch (144B rows)
    __nv_bfloat16* sW = (__nv_bfloat16*)(smem + 25920);    // 9*32 rows x 72 (144B rows)
    __shared__ float sSc[64], sAd[64];

    int tid = threadIdx.x;
    int n = blockIdx.z;
    int ty0 = blockIdx.y * 8, tx0 = blockIdx.x * 16;

    {   // weights: 41472 B = 2592 uint4
        const uint4* wsrc = (const uint4*)g_w2b;
        uint4* wdst = (uint4*)sW;
        for (int i = tid; i < 2592; i += 256) wdst[i] = wsrc[i];
    }
    {   // activations: 180 rows x 8 segs of 16B
        for (int i = tid; i < 1440; i += 256) {
            int r = i >> 3, s = i & 7;
            int ly = r / 18, lx = r % 18;
            int gy = ty0 - 1 + ly, gx = tx0 - 1 + lx;
            uint4 val = make_uint4(0, 0, 0, 0);
            if (gy >= 0 && gy < 112 && gx >= 0 && gx < 112) {
                long pix = ((long)(n * 112 + gy)) * 112 + gx;
                val = *(const uint4*)(g_h1 + pix * 64 + s * 8);
            }
            *(uint4*)(sX + r * 72 + s * 8) = val;
        }
    }
    if (tid < 64) {
        float inv = g[tid] / sqrtf(v[tid] + EPSBN);
        sSc[tid] = g_alpha[1] * inv;
        sAd[tid] = b[tid] - m[tid] * inv;
    }
    __syncthreads();

    int warp = tid >> 5, lane = tid & 31;
    int wm = warp & 3, wn = warp >> 2;
    int prow = lane & 15, khalf = lane >> 4;

    unsigned sXu = sptr(sX), sWu = sptr(sW);
    unsigned aBase0 = sXu + ((wm * 2 + 0) * 18 + prow) * 144 + khalf * 16;
    unsigned aBase1 = sXu + ((wm * 2 + 1) * 18 + prow) * 144 + khalf * 16;
    unsigned bBase0 = sWu + (prow * 72 + wn * 32 + khalf * 8) * 2;       // n-tiles 0,1
    unsigned bBase1 = bBase0 + 32;                                        // n-tiles 2,3 (+16 ch)

    float d[2][4][4];
#pragma unroll
    for (int i = 0; i < 2; ++i)
#pragma unroll
        for (int j = 0; j < 4; ++j)
#pragma unroll
            for (int k = 0; k < 4; ++k) d[i][j][k] = 0.f;

    for (int t = 0; t < 9; ++t) {
        int toff = ((t / 3) * 18 + (t % 3)) * 144;
#pragma unroll
        for (int gg = 0; gg < 2; ++gg) {
            unsigned woff = (unsigned)(t * 32 + gg * 16) * 144;
            unsigned b0, b1, b2, b3, b4, b5, b6, b7;
            ldsm4t(b0, b1, b2, b3, bBase0 + woff);
            ldsm4t(b4, b5, b6, b7, bBase1 + woff);
#pragma unroll
            for (int h = 0; h < 2; ++h) {
                unsigned koff = (unsigned)(gg * 64 + h * 32);
                unsigned a0, a1, a2, a3;
                ldsm4(a0, a1, a2, a3, aBase0 + toff + koff);
                mma_bf16(d[0][0], a0, a1, a2, a3, b0, b1);
                mma_bf16(d[0][1], a0, a1, a2, a3, b2, b3);
                mma_bf16(d[0][2], a0, a1, a2, a3, b4, b5);
                mma_bf16(d[0][3], a0, a1, a2, a3, b6, b7);
                ldsm4(a0, a1, a2, a3, aBase1 + toff + koff);
                mma_bf16(d[1][0], a0, a1, a2, a3, b0, b1);
                mma_bf16(d[1][1], a0, a1, a2, a3, b2, b3);
                mma_bf16(d[1][2], a0, a1, a2, a3, b4, b5);
                mma_bf16(d[1][3], a0, a1, a2, a3, b6, b7);
            }
        }
    }

    // epilogue: BN+ReLU, split to bf16 hi/lo, store NHWC
#pragma unroll
    for (int i = 0; i < 2; ++i) {
#pragma unroll
        for (int nt = 0; nt < 4; ++nt) {
            int oc = wn * 32 + nt * 8 + 2 * (lane & 3);
            float sc0 = sSc[oc], ad0 = sAd[oc];
            float sc1 = sSc[oc + 1], ad1 = sAd[oc + 1];
            int chh = ((oc >> 4) << 5) + (oc & 15);
#pragma unroll
            for (int rr = 0; rr < 2; ++rr) {
                int p = wm * 32 + i * 16 + (lane >> 2) + rr * 8;
                int oy = ty0 + (p >> 4), ox = tx0 + (p & 15);
                long pix = ((long)(n * 112 + oy)) * 112 + ox;
                float v0 = fmaxf(d[i][nt][rr * 2 + 0] * sc0 + ad0, 0.f);
                float v1 = fmaxf(d[i][nt][rr * 2 + 1] * sc1 + ad1, 0.f);
                float h0 = __bfloat162float(__float2bfloat16(v0));
                float h1 = __bfloat162float(__float2bfloat16(v1));
                *(unsigned*)(g_h2 + pix * 128 + chh) = pack_bf16x2(v0, v1);
                *(unsigned*)(g_h2 + pix * 128 + chh + 16) = pack_bf16x2(v0 - h0, v1 - h1);
            }
        }
    }
}

// ---------------- conv3 (tensor core): h2 -> BN+ReLU -> global-avg-pool (fused) ----------------
// Block: 8x8 out pixels (M=64), N=128 ocs, 256 thr (4 m-groups x 2 n-groups, warp 16px x 64oc).
// 3x3 s2 p1. Weights staged per tap. Pool sums accumulated via shfl + atomicAdd.
__global__ __launch_bounds__(256) void conv3_mma(
    const float* __restrict__ g, const float* __restrict__ b,
    const float* __restrict__ m, const float* __restrict__ v) {
    extern __shared__ __align__(16) char smem[];
    __nv_bfloat16* sX = (__nv_bfloat16*)smem;              // 289 rows x 136 ch (272B rows)
    __nv_bfloat16* sW = (__nv_bfloat16*)(smem + 78608);    // 64 rows x 136 (one tap)
    __shared__ float sSc[128], sAd[128];

    int tid = threadIdx.x;
    int n = blockIdx.z;
    int ty0 = blockIdx.y * 8, tx0 = blockIdx.x * 8;
    int iy0 = 2 * ty0 - 1, ix0 = 2 * tx0 - 1;

    // activations: 289 rows x 16 segs of 16B = 4624 uint4
    for (int i = tid; i < 4624; i += 256) {
        int r = i >> 4, s = i & 15;
        int ly = r / 17, lx = r % 17;
        int gy = iy0 + ly, gx = ix0 + lx;
        uint4 val = make_uint4(0, 0, 0, 0);
        if (gy >= 0 && gy < 112 && gx >= 0 && gx < 112) {
            long pix = ((long)(n * 112 + gy)) * 112 + gx;
            val = *(const uint4*)(g_h2 + pix * 128 + s * 8);
        }
        *(uint4*)(sX + r * 136 + s * 8) = val;
    }
    if (tid < 128) {
        float inv = g[tid] / sqrtf(v[tid] + EPSBN);
        sSc[tid] = g_alpha[2] * inv;
        sAd[tid] = b[tid] - m[tid] * inv;
    }

    int warp = tid >> 5, lane = tid & 31;
    int wm = warp & 3, wn = warp >> 2;
    int prow = lane & 15, khalf = lane >> 4;
    int p = wm * 16 + prow;
    int ppy = p >> 3, ppx = p & 7;

    unsigned sXu = sptr(sX), sWu = sptr(sW);
    unsigned aBase = sXu + ((2 * ppy) * 17 + 2 * ppx) * 272 + khalf * 16;
    unsigned bBase = sWu + (prow * 136 + wn * 64 + khalf * 8) * 2;

    float d[8][4];
#pragma unroll
    for (int j = 0; j < 8; ++j)
#pragma unroll
        for (int k = 0; k < 4; ++k) d[j][k] = 0.f;

    for (int t = 0; t < 9; ++t) {
        __syncthreads();
        {   // stage tap weights: 64 rows x 17 uint4 = 1088
            const uint4* wsrc = (const uint4*)(g_w3b + t * 64 * 136);
            uint4* wdst = (uint4*)sW;
            for (int i = tid; i < 1088; i += 256) wdst[i] = wsrc[i];
        }
        __syncthreads();
        int toff = ((t / 3) * 17 + (t % 3)) * 272;
#pragma unroll
        for (int gg = 0; gg < 4; ++gg) {
            unsigned woff = (unsigned)(gg * 16) * 272;
            unsigned bb[16];
            ldsm4t(bb[0], bb[1], bb[2], bb[3], bBase + woff);
            ldsm4t(bb[4], bb[5], bb[6], bb[7], bBase + woff + 32);
            ldsm4t(bb[8], bb[9], bb[10], bb[11], bBase + woff + 64);
            ldsm4t(bb[12], bb[13], bb[14], bb[15], bBase + woff + 96);
#pragma unroll
            for (int h = 0; h < 2; ++h) {
                unsigned koff = (unsigned)(gg * 64 + h * 32);
                unsigned a0, a1, a2, a3;
                ldsm4(a0, a1, a2, a3, aBase + toff + koff);
#pragma unroll
                for (int nt = 0; nt < 8; ++nt)
                    mma_bf16(d[nt], a0, a1, a2, a3, bb[nt * 2], bb[nt * 2 + 1]);
            }
        }
    }

    // epilogue: BN+ReLU, sum over pixels (warp covers 16 px), atomicAdd into pool
#pragma unroll
    for (int nt = 0; nt < 8; ++nt) {
        int oc = wn * 64 + nt * 8 + 2 * (lane & 3);
        float sc0 = sSc[oc], ad0 = sAd[oc];
        float sc1 = sSc[oc + 1], ad1 = sAd[oc + 1];
        float s0 = fmaxf(d[nt][0] * sc0 + ad0, 0.f) + fmaxf(d[nt][2] * sc0 + ad0, 0.f);
        float s1 = fmaxf(d[nt][1] * sc1 + ad1, 0.f) + fmaxf(d[nt][3] * sc1 + ad1, 0.f);
#pragma unroll
        for (int off = 4; off < 32; off <<= 1) {
            s0 += __shfl_xor_sync(0xffffffff, s0, off);
            s1 += __shfl_xor_sync(0xffffffff, s1, off);
        }
        if (lane < 4) {
            atomicAdd(&g_pool[n * 128 + oc], s0);
            atomicAdd(&g_pool[n * 128 + oc + 1], s1);
        }
    }
}

// ---------------- final linear: out[n,c] = (pool/3136) @ qwl.T + bl ----------------
__global__ void final_kernel(const float* __restrict__ bl, float* __restrict__ out) {
    int tid = blockIdx.x * blockDim.x + threadIdx.x;
    if (tid >= 640) return;
    int n = tid / 10, c = tid % 10;
    const float* p = g_pool + n * 128;
    const float* w = g_qwl + c * 128;
    float s = 0.f;
#pragma unroll 8
    for (int k = 0; k < 128; ++k) s += p[k] * w[k];
    out[tid] = s * (1.0f / 3136.0f) + bl[c];
}

// ---------------- launch ----------------
extern "C" void kernel_launch(void* const* d_in, const int* in_sizes, int n_in,
                              void* d_out, int out_size) {
    const float* x  = (const float*)d_in[0];
    const float* w1 = (const float*)d_in[1];
    const float* g1 = (const float*)d_in[2];
    const float* b1 = (const float*)d_in[3];
    const float* m1 = (const float*)d_in[4];
    const float* v1 = (const float*)d_in[5];
    const float* w2 = (const float*)d_in[6];
    const float* g2 = (const float*)d_in[7];
    const float* b2 = (const float*)d_in[8];
    const float* m2 = (const float*)d_in[9];
    const float* v2 = (const float*)d_in[10];
    const float* w3 = (const float*)d_in[11];
    const float* g3 = (const float*)d_in[12];
    const float* b3 = (const float*)d_in[13];
    const float* m3 = (const float*)d_in[14];
    const float* v3 = (const float*)d_in[15];
    const float* wl = (const float*)d_in[16];
    const float* bl = (const float*)d_in[17];
    float* out = (float*)d_out;

    cudaFuncSetAttribute((const void*)conv2_mma,
                         cudaFuncAttributeMaxDynamicSharedMemorySize, 67392);
    cudaFuncSetAttribute((const void*)conv3_mma,
                         cudaFuncAttributeMaxDynamicSharedMemorySize, 96016);

    prep_kernel<<<4, 1024>>>(w1, w2, w3, wl);
    conv1_kernel<<<dim3(7, 7, 64), 256>>>(x, g1, b1, m1, v1);
    conv2_mma<<<dim3(7, 14, 64), 256, 67392>>>(g2, b2, m2, v2);
    conv3_mma<<<dim3(7, 7, 64), 256, 96016>>>(g3, b3, m3, v3);
    final_kernel<<<3, 256>>>(bl, out);
}

// round 13
// speedup vs baseline: 3.4692x; 1.5618x over previous
#include <cuda_runtime.h>
#include <cuda_fp16.h>
#include <math.h>

#define EPSBN 1e-5f

// ---------------- device scratch (no allocations allowed) ----------------
// h1: NHWC [64][112][112][32] fp16
__device__ __align__(16) __half g_h1[64 * 112 * 112 * 32];    // 51.4 MB
// h2: NHWC [64][112][112][64] fp16
__device__ __align__(16) __half g_h2[64 * 112 * 112 * 64];    // 102.8 MB
__device__ float g_pool[64 * 128];
__device__ float g_qwl[10 * 128];
__device__ float g_w1r[9 * 3 * 32];                           // fp32 q (alpha included)
__device__ __align__(16) __half g_w2h[9 * 32 * 72];           // ternary t, oc 64 pad 72
__device__ __align__(16) __half g_w3h[9 * 64 * 136];          // ternary t, oc 128 pad 136
__device__ float g_alpha[4];

// ---------------- mma / ldmatrix / cp.async helpers ----------------
__device__ __forceinline__ unsigned sptr(const void* p) {
    return (unsigned)__cvta_generic_to_shared(p);
}
__device__ __forceinline__ void ldsm4(unsigned& r0, unsigned& r1, unsigned& r2, unsigned& r3, unsigned a) {
    asm volatile("ldmatrix.sync.aligned.m8n8.x4.shared.b16 {%0,%1,%2,%3},[%4];"
                 : "=r"(r0), "=r"(r1), "=r"(r2), "=r"(r3) : "r"(a));
}
__device__ __forceinline__ void ldsm4t(unsigned& r0, unsigned& r1, unsigned& r2, unsigned& r3, unsigned a) {
    asm volatile("ldmatrix.sync.aligned.m8n8.x4.trans.shared.b16 {%0,%1,%2,%3},[%4];"
                 : "=r"(r0), "=r"(r1), "=r"(r2), "=r"(r3) : "r"(a));
}
__device__ __forceinline__ void mma_f16(float* d, unsigned a0, unsigned a1, unsigned a2, unsigned a3,
                                        unsigned b0, unsigned b1) {
    asm volatile("mma.sync.aligned.m16n8k16.row.col.f32.f16.f16.f32 "
                 "{%0,%1,%2,%3},{%4,%5,%6,%7},{%8,%9},{%0,%1,%2,%3};"
                 : "+f"(d[0]), "+f"(d[1]), "+f"(d[2]), "+f"(d[3])
                 : "r"(a0), "r"(a1), "r"(a2), "r"(a3), "r"(b0), "r"(b1));
}
__device__ __forceinline__ unsigned pack_half2(float a, float b) {
    __half2 h = __floats2half2_rn(a, b);
    return *reinterpret_cast<unsigned*>(&h);
}
__device__ __forceinline__ void cpasync16(unsigned dst, const void* src) {
    asm volatile("cp.async.cg.shared.global [%0], [%1], 16;" :: "r"(dst), "l"(src));
}
#define CP_COMMIT() asm volatile("cp.async.commit_group;" ::: "memory")
#define CP_WAIT0()  asm volatile("cp.async.wait_group 0;" ::: "memory")

// ---------------- prep: ternarize all 4 weights in parallel (grid=4) ----------------
__global__ __launch_bounds__(1024) void prep_kernel(
    const float* __restrict__ w1, const float* __restrict__ w2,
    const float* __restrict__ w3, const float* __restrict__ wl) {
    __shared__ double reda[1024];
    __shared__ double redc[1024];
    __shared__ float s_delta, s_alpha;
    int which = blockIdx.x;
    const float* w = (which == 0) ? w1 : (which == 1) ? w2 : (which == 2) ? w3 : wl;
    int n = (which == 0) ? 864 : (which == 1) ? 18432 : (which == 2) ? 73728 : 1280;
    int tid = threadIdx.x;

    double s = 0.0;
    for (int i = tid; i < n; i += 1024) s += (double)fabsf(w[i]);
    reda[tid] = s; __syncthreads();
    for (int off = 512; off > 0; off >>= 1) {
        if (tid < off) reda[tid] += reda[tid + off];
        __syncthreads();
    }
    if (tid == 0) s_delta = (float)(0.7 * reda[0] / (double)n);
    __syncthreads();
    float delta = s_delta;

    double sa = 0.0, cnt = 0.0;
    for (int i = tid; i < n; i += 1024) {
        float a = fabsf(w[i]);
        if (a > delta) { sa += (double)a; cnt += 1.0; }
    }
    reda[tid] = sa; redc[tid] = cnt; __syncthreads();
    for (int off = 512; off > 0; off >>= 1) {
        if (tid < off) { reda[tid] += reda[tid + off]; redc[tid] += redc[tid + off]; }
        __syncthreads();
    }
    if (tid == 0) s_alpha = (float)(reda[0] / fmax(redc[0], 1.0));
    __syncthreads();
    float alpha = s_alpha;
    if (tid == 0) g_alpha[which] = alpha;

    if (which == 0) {
        for (int i = tid; i < n; i += 1024) {
            float wv = w[i];
            float qv = (fabsf(wv) > delta) ? copysignf(alpha, wv) : 0.0f;
            int r = i % 9; int t = i / 9; int ic = t % 3; int oc = t / 3;
            g_w1r[(r * 3 + ic) * 32 + oc] = qv;
        }
    } else if (which == 1) {
        for (int i = tid; i < n; i += 1024) {
            float wv = w[i];
            float tv = (fabsf(wv) > delta) ? (wv > 0.f ? 1.f : -1.f) : 0.0f;
            int r = i % 9; int t = i / 9; int ic = t % 32; int oc = t / 32;
            g_w2h[(r * 32 + ic) * 72 + oc] = __float2half(tv);
        }
    } else if (which == 2) {
        for (int i = tid; i < n; i += 1024) {
            float wv = w[i];
            float tv = (fabsf(wv) > delta) ? (wv > 0.f ? 1.f : -1.f) : 0.0f;
            int r = i % 9; int t = i / 9; int ic = t % 64; int oc = t / 64;
            g_w3h[(r * 64 + ic) * 136 + oc] = __float2half(tv);
        }
    } else {
        for (int i = tid; i < n; i += 1024) {
            float wv = w[i];
            g_qwl[i] = (fabsf(wv) > delta) ? copysignf(alpha, wv) : 0.0f;
        }
        for (int i = tid; i < 64 * 128; i += 1024) g_pool[i] = 0.f;  // zero pool accum
    }
}

// ---------------- conv1: [64,3,224,224] -> h1 NHWC fp16, s2 p1, BN+ReLU ----------------
__global__ __launch_bounds__(256) void conv1_kernel(
    const float* __restrict__ x, const float* __restrict__ g, const float* __restrict__ b,
    const float* __restrict__ m, const float* __restrict__ v) {
    __shared__ __align__(16) float sX[3 * 33 * 33];
    __shared__ __align__(16) float sW[9 * 3 * 32];
    __shared__ float sBNi[32], sBNa[32];

    int tid = threadIdx.x;
    int n = blockIdx.z;
    int ty0 = blockIdx.y * 16, tx0 = blockIdx.x * 16;
    int iy0 = 2 * ty0 - 1, ix0 = 2 * tx0 - 1;

    for (int i = tid; i < 3 * 33 * 33; i += 256) {
        int lx = i % 33; int t = i / 33; int ly = t % 33; int ic = t / 33;
        int gy = iy0 + ly, gx = ix0 + lx;
        float val = 0.f;
        if (gy >= 0 && gy < 224 && gx >= 0 && gx < 224)
            val = x[((n * 3 + ic) * 224 + gy) * 224 + gx];
        sX[i] = val;
    }
    for (int i = tid; i < 9 * 3 * 32; i += 256) sW[i] = g_w1r[i];
    if (tid < 32) {
        float inv = g[tid] / sqrtf(v[tid] + EPSBN);
        sBNi[tid] = inv; sBNa[tid] = b[tid] - m[tid] * inv;
    }
    __syncthreads();

    int py = tid / 16, px = tid % 16;
    float acc[32];
#pragma unroll
    for (int k = 0; k < 32; ++k) acc[k] = 0.f;

    for (int ic = 0; ic < 3; ++ic) {
#pragma unroll
        for (int r = 0; r < 9; ++r) {
            float xv = sX[ic * 1089 + (2 * py + r / 3) * 33 + (2 * px + r % 3)];
            const float4* w4 = (const float4*)&sW[(r * 3 + ic) * 32];
#pragma unroll
            for (int j = 0; j < 8; ++j) {
                float4 w = w4[j];
                acc[4 * j + 0] += xv * w.x;
                acc[4 * j + 1] += xv * w.y;
                acc[4 * j + 2] += xv * w.z;
                acc[4 * j + 3] += xv * w.w;
            }
        }
    }

    int oy = ty0 + py, ox = tx0 + px;
    long pix = ((long)(n * 112 + oy)) * 112 + ox;
    unsigned short buf[32];
#pragma unroll
    for (int oc = 0; oc < 32; ++oc) {
        float val = fmaxf(acc[oc] * sBNi[oc] + sBNa[oc], 0.f);
        __half h = __float2half(val);
        buf[oc] = *reinterpret_cast<unsigned short*>(&h);
    }
    uint4* dst = (uint4*)(g_h1 + pix * 32);
    const uint4* srcb = (const uint4*)buf;
#pragma unroll
    for (int j = 0; j < 4; ++j) dst[j] = srcb[j];
}

// ---------------- conv2 (tensor core): h1 -> h2, 3x3 s1 p1, BN+ReLU ----------------
// Block 8x16 px (M=128), N=64 oc, 8 warps (4 m x 2 n). K = 9 taps x 32 ch.
__global__ __launch_bounds__(256) void conv2_mma(
    const float* __restrict__ g, const float* __restrict__ b,
    const float* __restrict__ m, const float* __restrict__ v) {
    extern __shared__ __align__(16) char smem[];
    __half* sX = (__half*)smem;                  // 180 rows x 40 ch (80B rows)
    __half* sW = (__half*)(smem + 14400);        // 288 rows x 72 (144B rows)
    __shared__ float sSc[64], sAd[64];

    int tid = threadIdx.x;
    int n = blockIdx.z;
    int ty0 = blockIdx.y * 8, tx0 = blockIdx.x * 16;

    {   // weights: 41472 B = 2592 uint4
        const uint4* wsrc = (const uint4*)g_w2h;
        uint4* wdst = (uint4*)sW;
        for (int i = tid; i < 2592; i += 256) wdst[i] = wsrc[i];
    }
    {   // activations: 180 px x 4 segs of 16B (32 ch fp16 = 64 B/pixel)
        for (int i = tid; i < 720; i += 256) {
            int r = i >> 2, s = i & 3;
            int ly = r / 18, lx = r % 18;
            int gy = ty0 - 1 + ly, gx = tx0 - 1 + lx;
            uint4 val = make_uint4(0, 0, 0, 0);
            if (gy >= 0 && gy < 112 && gx >= 0 && gx < 112) {
                long pix = ((long)(n * 112 + gy)) * 112 + gx;
                val = *(const uint4*)(g_h1 + pix * 32 + s * 8);
            }
            *(uint4*)(sX + r * 40 + s * 8) = val;
        }
    }
    if (tid < 64) {
        float inv = g[tid] / sqrtf(v[tid] + EPSBN);
        sSc[tid] = g_alpha[1] * inv;
        sAd[tid] = b[tid] - m[tid] * inv;
    }
    __syncthreads();

    int warp = tid >> 5, lane = tid & 31;
    int wm = warp & 3, wn = warp >> 2;
    int prow = lane & 15, khalf = lane >> 4;

    unsigned sXu = sptr(sX), sWu = sptr(sW);
    unsigned aB0 = sXu + (((wm * 2 + 0) * 18 + prow) * 40 + khalf * 8) * 2;
    unsigned aB1 = sXu + (((wm * 2 + 1) * 18 + prow) * 40 + khalf * 8) * 2;
    unsigned bOff = (unsigned)(prow * 72 + wn * 32 + khalf * 8) * 2;

    float d[2][4][4];
#pragma unroll
    for (int i = 0; i < 2; ++i)
#pragma unroll
        for (int j = 0; j < 4; ++j)
#pragma unroll
            for (int k = 0; k < 4; ++k) d[i][j][k] = 0.f;

#pragma unroll
    for (int t = 0; t < 9; ++t) {
        unsigned toff = (unsigned)((t / 3) * 18 + (t % 3)) * 80;
#pragma unroll
        for (int kk = 0; kk < 2; ++kk) {
            unsigned wrow = sWu + (unsigned)(t * 32 + kk * 16) * 144 + bOff;
            unsigned b0, b1, b2, b3, b4, b5, b6, b7;
            ldsm4t(b0, b1, b2, b3, wrow);
            ldsm4t(b4, b5, b6, b7, wrow + 32);
            unsigned a0, a1, a2, a3;
            ldsm4(a0, a1, a2, a3, aB0 + toff + kk * 32);
            mma_f16(d[0][0], a0, a1, a2, a3, b0, b1);
            mma_f16(d[0][1], a0, a1, a2, a3, b2, b3);
            mma_f16(d[0][2], a0, a1, a2, a3, b4, b5);
            mma_f16(d[0][3], a0, a1, a2, a3, b6, b7);
            ldsm4(a0, a1, a2, a3, aB1 + toff + kk * 32);
            mma_f16(d[1][0], a0, a1, a2, a3, b0, b1);
            mma_f16(d[1][1], a0, a1, a2, a3, b2, b3);
            mma_f16(d[1][2], a0, a1, a2, a3, b4, b5);
            mma_f16(d[1][3], a0, a1, a2, a3, b6, b7);
        }
    }

    // epilogue: BN+ReLU, store h2 NHWC fp16
#pragma unroll
    for (int i = 0; i < 2; ++i) {
#pragma unroll
        for (int nt = 0; nt < 4; ++nt) {
            int oc = wn * 32 + nt * 8 + 2 * (lane & 3);
            float sc0 = sSc[oc], ad0 = sAd[oc];
            float sc1 = sSc[oc + 1], ad1 = sAd[oc + 1];
#pragma unroll
            for (int rr = 0; rr < 2; ++rr) {
                int p = wm * 32 + i * 16 + (lane >> 2) + rr * 8;
                int oy = ty0 + (p >> 4), ox = tx0 + (p & 15);
                long pix = ((long)(n * 112 + oy)) * 112 + ox;
                float v0 = fmaxf(d[i][nt][rr * 2 + 0] * sc0 + ad0, 0.f);
                float v1 = fmaxf(d[i][nt][rr * 2 + 1] * sc1 + ad1, 0.f);
                *(unsigned*)(g_h2 + pix * 64 + oc) = pack_half2(v0, v1);
            }
        }
    }
}

// ---------------- conv3 (tensor core): h2 -> BN+ReLU -> global-avg-pool (fused) ----------------
// Block 8x8 px (M=64), N=128 oc, 8 warps (2 m x 4 n). 3x3 s2 p1.
// Input tile stored as 4 parity planes (9x9 each) -> conflict-free A ldsm.
// Weights double-buffered per tap via cp.async.
__global__ __launch_bounds__(256) void conv3_mma(
    const float* __restrict__ g, const float* __restrict__ b,
    const float* __restrict__ m, const float* __restrict__ v) {
    extern __shared__ __align__(16) char smem[];
    __half* sX = (__half*)smem;                  // 4 planes x 81 rows x 72 ch = 46656 B
    unsigned sW0;                                // 2 bufs x 17408 B at +46656
    __shared__ float sSc[128], sAd[128];

    int tid = threadIdx.x;
    int n = blockIdx.z;
    int ty0 = blockIdx.y * 8, tx0 = blockIdx.x * 8;
    int iy0 = 2 * ty0 - 1, ix0 = 2 * tx0 - 1;

    sW0 = sptr(smem + 46656);

    // activations into parity planes: 4*81 px x 8 segs of 16B = 2592 uint4
    for (int i = tid; i < 2592; i += 256) {
        int px_i = i >> 3, s = i & 7;
        int plane = px_i / 81, rr = px_i % 81;
        int ly = rr / 9, lx = rr % 9;
        int ey = plane >> 1, ex = plane & 1;
        int gy = iy0 + 2 * ly + ey, gx = ix0 + 2 * lx + ex;
        uint4 val = make_uint4(0, 0, 0, 0);
        if (gy >= 0 && gy < 112 && gx >= 0 && gx < 112) {
            long pix = ((long)(n * 112 + gy)) * 112 + gx;
            val = *(const uint4*)(g_h2 + pix * 64 + s * 8);
        }
        *(uint4*)(sX + (plane * 81 + rr) * 72 + s * 8) = val;
    }
    if (tid < 128) {
        float inv = g[tid] / sqrtf(v[tid] + EPSBN);
        sSc[tid] = g_alpha[2] * inv;
        sAd[tid] = b[tid] - m[tid] * inv;
    }

    // preload tap 0 weights into buf 0
    {
        const char* src = (const char*)(g_w3h);
        for (int i = tid; i < 1088; i += 256) cpasync16(sW0 + i * 16, src + i * 16);
        CP_COMMIT();
    }

    int warp = tid >> 5, lane = tid & 31;
    int wm = warp & 1, wn = warp >> 1;
    int prow = lane & 15, khalf = lane >> 4;
    int p0 = wm * 32 + prow, p1 = p0 + 16;
    int ppy0 = p0 >> 3, ppx0 = p0 & 7;
    int ppy1 = p1 >> 3, ppx1 = p1 & 7;

    unsigned sXu = sptr(sX);
    unsigned bOff = (unsigned)(prow * 136 + wn * 32 + khalf * 8) * 2;

    float d[2][4][4];
#pragma unroll
    for (int i = 0; i < 2; ++i)
#pragma unroll
        for (int j = 0; j < 4; ++j)
#pragma unroll
            for (int k = 0; k < 4; ++k) d[i][j][k] = 0.f;

    for (int t = 0; t < 9; ++t) {
        CP_WAIT0();
        __syncthreads();
        if (t < 8) {   // stage tap t+1 into other buffer
            const char* src = (const char*)(g_w3h + (t + 1) * 64 * 136);
            unsigned dst = sW0 + ((unsigned)(t + 1) & 1) * 17408;
            for (int i = tid; i < 1088; i += 256) cpasync16(dst + i * 16, src + i * 16);
            CP_COMMIT();
        }
        int dy = t / 3, dx = t % 3;
        int plane = (dy & 1) * 2 + (dx & 1);
        int oy = dy >> 1, ox = dx >> 1;
        unsigned aA0 = sXu + ((unsigned)(plane * 81 + (ppy0 + oy) * 9 + ppx0 + ox) * 72 + khalf * 8) * 2;
        unsigned aA1 = sXu + ((unsigned)(plane * 81 + (ppy1 + oy) * 9 + ppx1 + ox) * 72 + khalf * 8) * 2;
        unsigned wbase = sW0 + ((unsigned)t & 1) * 17408 + bOff;
#pragma unroll
        for (int kk = 0; kk < 4; ++kk) {
            unsigned wrow = wbase + (unsigned)kk * (16 * 272);
            unsigned b0, b1, b2, b3, b4, b5, b6, b7;
            ldsm4t(b0, b1, b2, b3, wrow);
            ldsm4t(b4, b5, b6, b7, wrow + 32);
            unsigned a0, a1, a2, a3;
            ldsm4(a0, a1, a2, a3, aA0 + kk * 32);
            mma_f16(d[0][0], a0, a1, a2, a3, b0, b1);
            mma_f16(d[0][1], a0, a1, a2, a3, b2, b3);
            mma_f16(d[0][2], a0, a1, a2, a3, b4, b5);
            mma_f16(d[0][3], a0, a1, a2, a3, b6, b7);
            ldsm4(a0, a1, a2, a3, aA1 + kk * 32);
            mma_f16(d[1][0], a0, a1, a2, a3, b0, b1);
            mma_f16(d[1][1], a0, a1, a2, a3, b2, b3);
            mma_f16(d[1][2], a0, a1, a2, a3, b4, b5);
            mma_f16(d[1][3], a0, a1, a2, a3, b6, b7);
        }
    }

    // epilogue: BN+ReLU, sum over this block's 64 pixels, atomicAdd into pool
#pragma unroll
    for (int nt = 0; nt < 4; ++nt) {
        int oc = wn * 32 + nt * 8 + 2 * (lane & 3);
        float sc0 = sSc[oc], ad0 = sAd[oc];
        float sc1 = sSc[oc + 1], ad1 = sAd[oc + 1];
        float s0 = 0.f, s1 = 0.f;
#pragma unroll
        for (int i = 0; i < 2; ++i) {
            s0 += fmaxf(d[i][nt][0] * sc0 + ad0, 0.f) + fmaxf(d[i][nt][2] * sc0 + ad0, 0.f);
            s1 += fmaxf(d[i][nt][1] * sc1 + ad1, 0.f) + fmaxf(d[i][nt][3] * sc1 + ad1, 0.f);
        }
#pragma unroll
        for (int off = 4; off < 32; off <<= 1) {
            s0 += __shfl_xor_sync(0xffffffff, s0, off);
            s1 += __shfl_xor_sync(0xffffffff, s1, off);
        }
        if (lane < 4) {
            atomicAdd(&g_pool[n * 128 + oc], s0);
            atomicAdd(&g_pool[n * 128 + oc + 1], s1);
        }
    }
}

// ---------------- final linear: out[n,c] = (pool/3136) @ qwl.T + bl ----------------
__global__ void final_kernel(const float* __restrict__ bl, float* __restrict__ out) {
    int tid = blockIdx.x * blockDim.x + threadIdx.x;
    if (tid >= 640) return;
    int n = tid / 10, c = tid % 10;
    const float* p = g_pool + n * 128;
    const float* w = g_qwl + c * 128;
    float s = 0.f;
#pragma unroll 8
    for (int k = 0; k < 128; ++k) s += p[k] * w[k];
    out[tid] = s * (1.0f / 3136.0f) + bl[c];
}

// ---------------- launch ----------------
extern "C" void kernel_launch(void* const* d_in, const int* in_sizes, int n_in,
                              void* d_out, int out_size) {
    const float* x  = (const float*)d_in[0];
    const float* w1 = (const float*)d_in[1];
    const float* g1 = (const float*)d_in[2];
    const float* b1 = (const float*)d_in[3];
    const float* m1 = (const float*)d_in[4];
    const float* v1 = (const float*)d_in[5];
    const float* w2 = (const float*)d_in[6];
    const float* g2 = (const float*)d_in[7];
    const float* b2 = (const float*)d_in[8];
    const float* m2 = (const float*)d_in[9];
    const float* v2 = (const float*)d_in[10];
    const float* w3 = (const float*)d_in[11];
    const float* g3 = (const float*)d_in[12];
    const float* b3 = (const float*)d_in[13];
    const float* m3 = (const float*)d_in[14];
    const float* v3 = (const float*)d_in[15];
    const float* wl = (const float*)d_in[16];
    const float* bl = (const float*)d_in[17];
    float* out = (float*)d_out;

    cudaFuncSetAttribute((const void*)conv2_mma,
                         cudaFuncAttributeMaxDynamicSharedMemorySize, 55872);
    cudaFuncSetAttribute((const void*)conv3_mma,
                         cudaFuncAttributeMaxDynamicSharedMemorySize, 81472);

    prep_kernel<<<4, 1024>>>(w1, w2, w3, wl);
    conv1_kernel<<<dim3(7, 7, 64), 256>>>(x, g1, b1, m1, v1);
    conv2_mma<<<dim3(7, 14, 64), 256, 55872>>>(g2, b2, m2, v2);
    conv3_mma<<<dim3(7, 7, 64), 256, 81472>>>(g3, b3, m3, v3);
    final_kernel<<<3, 256>>>(bl, out);
}

// round 14
// speedup vs baseline: 3.6719x; 1.0584x over previous
#include <cuda_runtime.h>
#include <cuda_fp16.h>
#include <math.h>

#define EPSBN 1e-5f

// ---------------- device scratch (no allocations allowed) ----------------
// h1: NHWC [64][112][112][32] fp16
__device__ __align__(16) __half g_h1[64 * 112 * 112 * 32];    // 51.4 MB
// h2: NHWC [64][112][112][64] fp16
__device__ __align__(16) __half g_h2[64 * 112 * 112 * 64];    // 102.8 MB
__device__ float g_pool[64 * 128];
__device__ float g_qwl[10 * 128];
__device__ float g_w1r[9 * 3 * 32];                           // fp32 q (alpha included)
__device__ __align__(16) __half g_w2h[9 * 32 * 72];           // ternary t, oc 64 pad 72
__device__ __align__(16) __half g_w3h[9 * 64 * 136];          // ternary t, oc 128 pad 136
__device__ float g_alpha[4];

// ---------------- mma / ldmatrix helpers ----------------
__device__ __forceinline__ unsigned sptr(const void* p) {
    return (unsigned)__cvta_generic_to_shared(p);
}
__device__ __forceinline__ void ldsm4(unsigned& r0, unsigned& r1, unsigned& r2, unsigned& r3, unsigned a) {
    asm volatile("ldmatrix.sync.aligned.m8n8.x4.shared.b16 {%0,%1,%2,%3},[%4];"
                 : "=r"(r0), "=r"(r1), "=r"(r2), "=r"(r3) : "r"(a));
}
__device__ __forceinline__ void ldsm4t(unsigned& r0, unsigned& r1, unsigned& r2, unsigned& r3, unsigned a) {
    asm volatile("ldmatrix.sync.aligned.m8n8.x4.trans.shared.b16 {%0,%1,%2,%3},[%4];"
                 : "=r"(r0), "=r"(r1), "=r"(r2), "=r"(r3) : "r"(a));
}
__device__ __forceinline__ void mma_f16(float* d, unsigned a0, unsigned a1, unsigned a2, unsigned a3,
                                        unsigned b0, unsigned b1) {
    asm volatile("mma.sync.aligned.m16n8k16.row.col.f32.f16.f16.f32 "
                 "{%0,%1,%2,%3},{%4,%5,%6,%7},{%8,%9},{%0,%1,%2,%3};"
                 : "+f"(d[0]), "+f"(d[1]), "+f"(d[2]), "+f"(d[3])
                 : "r"(a0), "r"(a1), "r"(a2), "r"(a3), "r"(b0), "r"(b1));
}
__device__ __forceinline__ unsigned pack_half2(float a, float b) {
    __half2 h = __floats2half2_rn(a, b);
    return *reinterpret_cast<unsigned*>(&h);
}

// ---------------- prep: ternarize all 4 weights in parallel (grid=4) ----------------
__global__ __launch_bounds__(1024) void prep_kernel(
    const float* __restrict__ w1, const float* __restrict__ w2,
    const float* __restrict__ w3, const float* __restrict__ wl) {
    __shared__ double reda[1024];
    __shared__ double redc[1024];
    __shared__ float s_delta, s_alpha;
    int which = blockIdx.x;
    const float* w = (which == 0) ? w1 : (which == 1) ? w2 : (which == 2) ? w3 : wl;
    int n = (which == 0) ? 864 : (which == 1) ? 18432 : (which == 2) ? 73728 : 1280;
    int tid = threadIdx.x;

    double s = 0.0;
    for (int i = tid; i < n; i += 1024) s += (double)fabsf(w[i]);
    reda[tid] = s; __syncthreads();
    for (int off = 512; off > 0; off >>= 1) {
        if (tid < off) reda[tid] += reda[tid + off];
        __syncthreads();
    }
    if (tid == 0) s_delta = (float)(0.7 * reda[0] / (double)n);
    __syncthreads();
    float delta = s_delta;

    double sa = 0.0, cnt = 0.0;
    for (int i = tid; i < n; i += 1024) {
        float a = fabsf(w[i]);
        if (a > delta) { sa += (double)a; cnt += 1.0; }
    }
    reda[tid] = sa; redc[tid] = cnt; __syncthreads();
    for (int off = 512; off > 0; off >>= 1) {
        if (tid < off) { reda[tid] += reda[tid + off]; redc[tid] += redc[tid + off]; }
        __syncthreads();
    }
    if (tid == 0) s_alpha = (float)(reda[0] / fmax(redc[0], 1.0));
    __syncthreads();
    float alpha = s_alpha;
    if (tid == 0) g_alpha[which] = alpha;

    if (which == 0) {
        for (int i = tid; i < n; i += 1024) {
            float wv = w[i];
            float qv = (fabsf(wv) > delta) ? copysignf(alpha, wv) : 0.0f;
            int r = i % 9; int t = i / 9; int ic = t % 3; int oc = t / 3;
            g_w1r[(r * 3 + ic) * 32 + oc] = qv;
        }
    } else if (which == 1) {
        for (int i = tid; i < n; i += 1024) {
            float wv = w[i];
            float tv = (fabsf(wv) > delta) ? (wv > 0.f ? 1.f : -1.f) : 0.0f;
            int r = i % 9; int t = i / 9; int ic = t % 32; int oc = t / 32;
            g_w2h[(r * 32 + ic) * 72 + oc] = __float2half(tv);
        }
    } else if (which == 2) {
        for (int i = tid; i < n; i += 1024) {
            float wv = w[i];
            float tv = (fabsf(wv) > delta) ? (wv > 0.f ? 1.f : -1.f) : 0.0f;
            int r = i % 9; int t = i / 9; int ic = t % 64; int oc = t / 64;
            g_w3h[(r * 64 + ic) * 136 + oc] = __float2half(tv);
        }
    } else {
        for (int i = tid; i < n; i += 1024) {
            float wv = w[i];
            g_qwl[i] = (fabsf(wv) > delta) ? copysignf(alpha, wv) : 0.0f;
        }
        for (int i = tid; i < 64 * 128; i += 1024) g_pool[i] = 0.f;  // zero pool accum
    }
}

// ---------------- conv1: [64,3,224,224] -> h1 NHWC fp16, s2 p1, BN+ReLU ----------------
__global__ __launch_bounds__(256) void conv1_kernel(
    const float* __restrict__ x, const float* __restrict__ g, const float* __restrict__ b,
    const float* __restrict__ m, const float* __restrict__ v) {
    __shared__ __align__(16) float sX[3 * 33 * 33];
    __shared__ __align__(16) float sW[9 * 3 * 32];
    __shared__ float sBNi[32], sBNa[32];

    int tid = threadIdx.x;
    int n = blockIdx.z;
    int ty0 = blockIdx.y * 16, tx0 = blockIdx.x * 16;
    int iy0 = 2 * ty0 - 1, ix0 = 2 * tx0 - 1;

    for (int i = tid; i < 3 * 33 * 33; i += 256) {
        int lx = i % 33; int t = i / 33; int ly = t % 33; int ic = t / 33;
        int gy = iy0 + ly, gx = ix0 + lx;
        float val = 0.f;
        if (gy >= 0 && gy < 224 && gx >= 0 && gx < 224)
            val = x[((n * 3 + ic) * 224 + gy) * 224 + gx];
        sX[i] = val;
    }
    for (int i = tid; i < 9 * 3 * 32; i += 256) sW[i] = g_w1r[i];
    if (tid < 32) {
        float inv = g[tid] / sqrtf(v[tid] + EPSBN);
        sBNi[tid] = inv; sBNa[tid] = b[tid] - m[tid] * inv;
    }
    __syncthreads();

    int py = tid / 16, px = tid % 16;
    float acc[32];
#pragma unroll
    for (int k = 0; k < 32; ++k) acc[k] = 0.f;

    for (int ic = 0; ic < 3; ++ic) {
#pragma unroll
        for (int r = 0; r < 9; ++r) {
            float xv = sX[ic * 1089 + (2 * py + r / 3) * 33 + (2 * px + r % 3)];
            const float4* w4 = (const float4*)&sW[(r * 3 + ic) * 32];
#pragma unroll
            for (int j = 0; j < 8; ++j) {
                float4 w = w4[j];
                acc[4 * j + 0] += xv * w.x;
                acc[4 * j + 1] += xv * w.y;
                acc[4 * j + 2] += xv * w.z;
                acc[4 * j + 3] += xv * w.w;
            }
        }
    }

    int oy = ty0 + py, ox = tx0 + px;
    long pix = ((long)(n * 112 + oy)) * 112 + ox;
    unsigned short buf[32];
#pragma unroll
    for (int oc = 0; oc < 32; ++oc) {
        float val = fmaxf(acc[oc] * sBNi[oc] + sBNa[oc], 0.f);
        __half h = __float2half(val);
        buf[oc] = *reinterpret_cast<unsigned short*>(&h);
    }
    uint4* dst = (uint4*)(g_h1 + pix * 32);
    const uint4* srcb = (const uint4*)buf;
#pragma unroll
    for (int j = 0; j < 4; ++j) dst[j] = srcb[j];
}

// ---------------- conv2 (tensor core): h1 -> h2, 3x3 s1 p1, BN+ReLU ----------------
// Block 8x16 px (M=128), N=64 oc, 8 warps (4 m x 2 n). K = 9 taps x 32 ch.
__global__ __launch_bounds__(256, 3) void conv2_mma(
    const float* __restrict__ g, const float* __restrict__ b,
    const float* __restrict__ m, const float* __restrict__ v) {
    extern __shared__ __align__(16) char smem[];
    __half* sX = (__half*)smem;                  // 180 rows x 40 ch (80B rows)
    __half* sW = (__half*)(smem + 14400);        // 288 rows x 72 (144B rows)
    __shared__ float sSc[64], sAd[64];

    int tid = threadIdx.x;
    int n = blockIdx.z;
    int ty0 = blockIdx.y * 8, tx0 = blockIdx.x * 16;

    {   // weights: 41472 B = 2592 uint4
        const uint4* wsrc = (const uint4*)g_w2h;
        uint4* wdst = (uint4*)sW;
        for (int i = tid; i < 2592; i += 256) wdst[i] = wsrc[i];
    }
    {   // activations: 180 px x 4 segs of 16B (32 ch fp16 = 64 B/pixel)
        for (int i = tid; i < 720; i += 256) {
            int r = i >> 2, s = i & 3;
            int ly = r / 18, lx = r % 18;
            int gy = ty0 - 1 + ly, gx = tx0 - 1 + lx;
            uint4 val = make_uint4(0, 0, 0, 0);
            if (gy >= 0 && gy < 112 && gx >= 0 && gx < 112) {
                long pix = ((long)(n * 112 + gy)) * 112 + gx;
                val = *(const uint4*)(g_h1 + pix * 32 + s * 8);
            }
            *(uint4*)(sX + r * 40 + s * 8) = val;
        }
    }
    if (tid < 64) {
        float inv = g[tid] / sqrtf(v[tid] + EPSBN);
        sSc[tid] = g_alpha[1] * inv;
        sAd[tid] = b[tid] - m[tid] * inv;
    }
    __syncthreads();

    int warp = tid >> 5, lane = tid & 31;
    int wm = warp & 3, wn = warp >> 2;
    int prow = lane & 15, khalf = lane >> 4;

    unsigned sXu = sptr(sX), sWu = sptr(sW);
    unsigned aB0 = sXu + (((wm * 2 + 0) * 18 + prow) * 40 + khalf * 8) * 2;
    unsigned aB1 = sXu + (((wm * 2 + 1) * 18 + prow) * 40 + khalf * 8) * 2;
    unsigned bOff = (unsigned)(prow * 72 + wn * 32 + khalf * 8) * 2;

    float d[2][4][4];
#pragma unroll
    for (int i = 0; i < 2; ++i)
#pragma unroll
        for (int j = 0; j < 4; ++j)
#pragma unroll
            for (int k = 0; k < 4; ++k) d[i][j][k] = 0.f;

#pragma unroll
    for (int t = 0; t < 9; ++t) {
        unsigned toff = (unsigned)((t / 3) * 18 + (t % 3)) * 80;
#pragma unroll
        for (int kk = 0; kk < 2; ++kk) {
            unsigned wrow = sWu + (unsigned)(t * 32 + kk * 16) * 144 + bOff;
            unsigned b0, b1, b2, b3, b4, b5, b6, b7;
            ldsm4t(b0, b1, b2, b3, wrow);
            ldsm4t(b4, b5, b6, b7, wrow + 32);
            unsigned a0, a1, a2, a3;
            ldsm4(a0, a1, a2, a3, aB0 + toff + kk * 32);
            mma_f16(d[0][0], a0, a1, a2, a3, b0, b1);
            mma_f16(d[0][1], a0, a1, a2, a3, b2, b3);
            mma_f16(d[0][2], a0, a1, a2, a3, b4, b5);
            mma_f16(d[0][3], a0, a1, a2, a3, b6, b7);
            ldsm4(a0, a1, a2, a3, aB1 + toff + kk * 32);
            mma_f16(d[1][0], a0, a1, a2, a3, b0, b1);
            mma_f16(d[1][1], a0, a1, a2, a3, b2, b3);
            mma_f16(d[1][2], a0, a1, a2, a3, b4, b5);
            mma_f16(d[1][3], a0, a1, a2, a3, b6, b7);
        }
    }

    // epilogue: BN+ReLU, store h2 NHWC fp16
#pragma unroll
    for (int i = 0; i < 2; ++i) {
#pragma unroll
        for (int nt = 0; nt < 4; ++nt) {
            int oc = wn * 32 + nt * 8 + 2 * (lane & 3);
            float sc0 = sSc[oc], ad0 = sAd[oc];
            float sc1 = sSc[oc + 1], ad1 = sAd[oc + 1];
#pragma unroll
            for (int rr = 0; rr < 2; ++rr) {
                int p = wm * 32 + i * 16 + (lane >> 2) + rr * 8;
                int oy = ty0 + (p >> 4), ox = tx0 + (p & 15);
                long pix = ((long)(n * 112 + oy)) * 112 + ox;
                float v0 = fmaxf(d[i][nt][rr * 2 + 0] * sc0 + ad0, 0.f);
                float v1 = fmaxf(d[i][nt][rr * 2 + 1] * sc1 + ad1, 0.f);
                *(unsigned*)(g_h2 + pix * 64 + oc) = pack_half2(v0, v1);
            }
        }
    }
}

// ---------------- conv3 (tensor core): h2 -> BN+ReLU -> global-avg-pool (fused) ----------------
// Block 8x8 px (M=64), N=128 oc, 8 warps (2 m x 4 n). 3x3 s2 p1.
// Input tile stored as 4 parity planes (9x9 each) -> conflict-free A ldsm.
// Single weight buffer + register-staged prefetch -> 64 KB smem -> 3 CTAs/SM.
__global__ __launch_bounds__(256, 3) void conv3_mma(
    const float* __restrict__ g, const float* __restrict__ b,
    const float* __restrict__ m, const float* __restrict__ v) {
    extern __shared__ __align__(16) char smem[];
    __half* sX = (__half*)smem;                  // 4 planes x 81 rows x 72 ch = 46656 B
    uint4* sW = (uint4*)(smem + 46656);          // 1088 uint4 = 17408 B (one tap)
    __shared__ float sSc[128], sAd[128];

    int tid = threadIdx.x;
    int n = blockIdx.z;
    int ty0 = blockIdx.y * 8, tx0 = blockIdx.x * 8;
    int iy0 = 2 * ty0 - 1, ix0 = 2 * tx0 - 1;

    // activations into parity planes: 4*81 px x 8 segs of 16B = 2592 uint4
    for (int i = tid; i < 2592; i += 256) {
        int px_i = i >> 3, s = i & 7;
        int plane = px_i / 81, rr = px_i % 81;
        int ly = rr / 9, lx = rr % 9;
        int ey = plane >> 1, ex = plane & 1;
        int gy = iy0 + 2 * ly + ey, gx = ix0 + 2 * lx + ex;
        uint4 val = make_uint4(0, 0, 0, 0);
        if (gy >= 0 && gy < 112 && gx >= 0 && gx < 112) {
            long pix = ((long)(n * 112 + gy)) * 112 + gx;
            val = *(const uint4*)(g_h2 + pix * 64 + s * 8);
        }
        *(uint4*)(sX + (plane * 81 + rr) * 72 + s * 8) = val;
    }
    if (tid < 128) {
        float inv = g[tid] / sqrtf(v[tid] + EPSBN);
        sSc[tid] = g_alpha[2] * inv;
        sAd[tid] = b[tid] - m[tid] * inv;
    }

    // reg-stage tap 0 and store to smem
    const uint4* wglob = (const uint4*)g_w3h;    // tap t at offset t*1088
    uint4 wreg[5];
#pragma unroll
    for (int k = 0; k < 5; ++k) {
        int i = tid + k * 256;
        wreg[k] = (i < 1088) ? wglob[i] : make_uint4(0, 0, 0, 0);
    }
#pragma unroll
    for (int k = 0; k < 5; ++k) {
        int i = tid + k * 256;
        if (i < 1088) sW[i] = wreg[k];
    }
    __syncthreads();

    int warp = tid >> 5, lane = tid & 31;
    int wm = warp & 1, wn = warp >> 1;
    int prow = lane & 15, khalf = lane >> 4;
    int p0 = wm * 32 + prow, p1 = p0 + 16;
    int ppy0 = p0 >> 3, ppx0 = p0 & 7;
    int ppy1 = p1 >> 3, ppx1 = p1 & 7;

    unsigned sXu = sptr(sX);
    unsigned sWu = sptr(sW);
    // per-thread invariant parts of A addresses (tap adds a compile-time constant)
    unsigned aInv0 = sXu + ((unsigned)(ppy0 * 9 + ppx0) * 72 + khalf * 8) * 2;
    unsigned aInv1 = sXu + ((unsigned)(ppy1 * 9 + ppx1) * 72 + khalf * 8) * 2;
    unsigned bOff = sWu + (unsigned)(prow * 136 + wn * 32 + khalf * 8) * 2;

    float d[2][4][4];
#pragma unroll
    for (int i = 0; i < 2; ++i)
#pragma unroll
        for (int j = 0; j < 4; ++j)
#pragma unroll
            for (int k = 0; k < 4; ++k) d[i][j][k] = 0.f;

#pragma unroll
    for (int t = 0; t < 9; ++t) {
        // prefetch next tap's weights into registers (overlaps with MMA below)
        if (t < 8) {
            const uint4* src = wglob + (t + 1) * 1088;
#pragma unroll
            for (int k = 0; k < 5; ++k) {
                int i = tid + k * 256;
                if (i < 1088) wreg[k] = src[i];
            }
        }
        const int dy = t / 3, dx = t % 3;                 // compile-time (unrolled)
        const int plane = (dy & 1) * 2 + (dx & 1);
        const int oy = dy >> 1, ox = dx >> 1;
        const unsigned tapOff = (unsigned)((plane * 81 + oy * 9 + ox) * 72) * 2;
        unsigned aA0 = aInv0 + tapOff;
        unsigned aA1 = aInv1 + tapOff;
#pragma unroll
        for (int kk = 0; kk < 4; ++kk) {
            unsigned wrow = bOff + (unsigned)kk * (16 * 272);
            unsigned b0, b1, b2, b3, b4, b5, b6, b7;
            ldsm4t(b0, b1, b2, b3, wrow);
            ldsm4t(b4, b5, b6, b7, wrow + 32);
            unsigned a0, a1, a2, a3;
            ldsm4(a0, a1, a2, a3, aA0 + kk * 32);
            mma_f16(d[0][0], a0, a1, a2, a3, b0, b1);
            mma_f16(d[0][1], a0, a1, a2, a3, b2, b3);
            mma_f16(d[0][2], a0, a1, a2, a3, b4, b5);
            mma_f16(d[0][3], a0, a1, a2, a3, b6, b7);
            ldsm4(a0, a1, a2, a3, aA1 + kk * 32);
            mma_f16(d[1][0], a0, a1, a2, a3, b0, b1);
            mma_f16(d[1][1], a0, a1, a2, a3, b2, b3);
            mma_f16(d[1][2], a0, a1, a2, a3, b4, b5);
            mma_f16(d[1][3], a0, a1, a2, a3, b6, b7);
        }
        __syncthreads();                       // all warps done reading sW for tap t
        if (t < 8) {
#pragma unroll
            for (int k = 0; k < 5; ++k) {
                int i = tid + k * 256;
                if (i < 1088) sW[i] = wreg[k];
            }
        }
        __syncthreads();                       // sW holds tap t+1
    }

    // epilogue: BN+ReLU, sum over this block's 64 pixels, atomicAdd into pool
#pragma unroll
    for (int nt = 0; nt < 4; ++nt) {
        int oc = wn * 32 + nt * 8 + 2 * (lane & 3);
        float sc0 = sSc[oc], ad0 = sAd[oc];
        float sc1 = sSc[oc + 1], ad1 = sAd[oc + 1];
        float s0 = 0.f, s1 = 0.f;
#pragma unroll
        for (int i = 0; i < 2; ++i) {
            s0 += fmaxf(d[i][nt][0] * sc0 + ad0, 0.f) + fmaxf(d[i][nt][2] * sc0 + ad0, 0.f);
            s1 += fmaxf(d[i][nt][1] * sc1 + ad1, 0.f) + fmaxf(d[i][nt][3] * sc1 + ad1, 0.f);
        }
#pragma unroll
        for (int off = 4; off < 32; off <<= 1) {
            s0 += __shfl_xor_sync(0xffffffff, s0, off);
            s1 += __shfl_xor_sync(0xffffffff, s1, off);
        }
        if (lane < 4) {
            atomicAdd(&g_pool[n * 128 + oc], s0);
            atomicAdd(&g_pool[n * 128 + oc + 1], s1);
        }
    }
}

// ---------------- final linear: out[n,c] = (pool/3136) @ qwl.T + bl ----------------
__global__ void final_kernel(const float* __restrict__ bl, float* __restrict__ out) {
    int tid = blockIdx.x * blockDim.x + threadIdx.x;
    if (tid >= 640) return;
    int n = tid / 10, c = tid % 10;
    const float* p = g_pool + n * 128;
    const float* w = g_qwl + c * 128;
    float s = 0.f;
#pragma unroll 8
    for (int k = 0; k < 128; ++k) s += p[k] * w[k];
    out[tid] = s * (1.0f / 3136.0f) + bl[c];
}

// ---------------- launch ----------------
extern "C" void kernel_launch(void* const* d_in, const int* in_sizes, int n_in,
                              void* d_out, int out_size) {
    const float* x  = (const float*)d_in[0];
    const float* w1 = (const float*)d_in[1];
    const float* g1 = (const float*)d_in[2];
    const float* b1 = (const float*)d_in[3];
    const float* m1 = (const float*)d_in[4];
    const float* v1 = (const float*)d_in[5];
    const float* w2 = (const float*)d_in[6];
    const float* g2 = (const float*)d_in[7];
    const float* b2 = (const float*)d_in[8];
    const float* m2 = (const float*)d_in[9];
    const float* v2 = (const float*)d_in[10];
    const float* w3 = (const float*)d_in[11];
    const float* g3 = (const float*)d_in[12];
    const float* b3 = (const float*)d_in[13];
    const float* m3 = (const float*)d_in[14];
    const float* v3 = (const float*)d_in[15];
    const float* wl = (const float*)d_in[16];
    const float* bl = (const float*)d_in[17];
    float* out = (float*)d_out;

    cudaFuncSetAttribute((const void*)conv2_mma,
                         cudaFuncAttributeMaxDynamicSharedMemorySize, 55872);
    cudaFuncSetAttribute((const void*)conv3_mma,
                         cudaFuncAttributeMaxDynamicSharedMemorySize, 64064);

    prep_kernel<<<4, 1024>>>(w1, w2, w3, wl);
    conv1_kernel<<<dim3(7, 7, 64), 256>>>(x, g1, b1, m1, v1);
    conv2_mma<<<dim3(7, 14, 64), 256, 55872>>>(g2, b2, m2, v2);
    conv3_mma<<<dim3(7, 7, 64), 256, 64064>>>(g3, b3, m3, v3);
    final_kernel<<<3, 256>>>(bl, out);
}

// round 17
// speedup vs baseline: 3.7332x; 1.0167x over previous
#include <cuda_runtime.h>
#include <cuda_fp16.h>
#include <math.h>

#define EPSBN 1e-5f

// ---------------- device scratch (no allocations allowed) ----------------
// h1: NHWC [64][112][112][32] fp16
__device__ __align__(16) __half g_h1[64 * 112 * 112 * 32];    // 51.4 MB
// h2: NHWC [64][112][112][64] fp16
__device__ __align__(16) __half g_h2[64 * 112 * 112 * 64];    // 102.8 MB
__device__ float g_pool[64 * 128];
__device__ float g_qwl[10 * 128];
__device__ float g_w1r[9 * 3 * 32];                           // fp32 q (alpha included)
__device__ __align__(16) __half g_w2h[9 * 32 * 72];           // ternary t, oc 64 pad 72
__device__ __align__(16) __half g_w3h[9 * 64 * 136];          // ternary t, oc 128 pad 136
__device__ float g_alpha[4];

// ---------------- mma / ldmatrix helpers ----------------
__device__ __forceinline__ unsigned sptr(const void* p) {
    return (unsigned)__cvta_generic_to_shared(p);
}
__device__ __forceinline__ void ldsm4(unsigned& r0, unsigned& r1, unsigned& r2, unsigned& r3, unsigned a) {
    asm volatile("ldmatrix.sync.aligned.m8n8.x4.shared.b16 {%0,%1,%2,%3},[%4];"
                 : "=r"(r0), "=r"(r1), "=r"(r2), "=r"(r3) : "r"(a));
}
__device__ __forceinline__ void ldsm4t(unsigned& r0, unsigned& r1, unsigned& r2, unsigned& r3, unsigned a) {
    asm volatile("ldmatrix.sync.aligned.m8n8.x4.trans.shared.b16 {%0,%1,%2,%3},[%4];"
                 : "=r"(r0), "=r"(r1), "=r"(r2), "=r"(r3) : "r"(a));
}
__device__ __forceinline__ void mma_f16(float* d, unsigned a0, unsigned a1, unsigned a2, unsigned a3,
                                        unsigned b0, unsigned b1) {
    asm volatile("mma.sync.aligned.m16n8k16.row.col.f32.f16.f16.f32 "
                 "{%0,%1,%2,%3},{%4,%5,%6,%7},{%8,%9},{%0,%1,%2,%3};"
                 : "+f"(d[0]), "+f"(d[1]), "+f"(d[2]), "+f"(d[3])
                 : "r"(a0), "r"(a1), "r"(a2), "r"(a3), "r"(b0), "r"(b1));
}
__device__ __forceinline__ unsigned pack_half2(float a, float b) {
    __half2 h = __floats2half2_rn(a, b);
    return *reinterpret_cast<unsigned*>(&h);
}

// ---------------- prep: ternarize all 4 weights in parallel (grid=4) ----------------
__global__ __launch_bounds__(1024) void prep_kernel(
    const float* __restrict__ w1, const float* __restrict__ w2,
    const float* __restrict__ w3, const float* __restrict__ wl) {
    __shared__ double reda[1024];
    __shared__ double redc[1024];
    __shared__ float s_delta, s_alpha;
    int which = blockIdx.x;
    const float* w = (which == 0) ? w1 : (which == 1) ? w2 : (which == 2) ? w3 : wl;
    int n = (which == 0) ? 864 : (which == 1) ? 18432 : (which == 2) ? 73728 : 1280;
    int tid = threadIdx.x;

    double s = 0.0;
    for (int i = tid; i < n; i += 1024) s += (double)fabsf(w[i]);
    reda[tid] = s; __syncthreads();
    for (int off = 512; off > 0; off >>= 1) {
        if (tid < off) reda[tid] += reda[tid + off];
        __syncthreads();
    }
    if (tid == 0) s_delta = (float)(0.7 * reda[0] / (double)n);
    __syncthreads();
    float delta = s_delta;

    double sa = 0.0, cnt = 0.0;
    for (int i = tid; i < n; i += 1024) {
        float a = fabsf(w[i]);
        if (a > delta) { sa += (double)a; cnt += 1.0; }
    }
    reda[tid] = sa; redc[tid] = cnt; __syncthreads();
    for (int off = 512; off > 0; off >>= 1) {
        if (tid < off) { reda[tid] += reda[tid + off]; redc[tid] += redc[tid + off]; }
        __syncthreads();
    }
    if (tid == 0) s_alpha = (float)(reda[0] / fmax(redc[0], 1.0));
    __syncthreads();
    float alpha = s_alpha;
    if (tid == 0) g_alpha[which] = alpha;

    if (which == 0) {
        for (int i = tid; i < n; i += 1024) {
            float wv = w[i];
            float qv = (fabsf(wv) > delta) ? copysignf(alpha, wv) : 0.0f;
            int r = i % 9; int t = i / 9; int ic = t % 3; int oc = t / 3;
            g_w1r[(r * 3 + ic) * 32 + oc] = qv;
        }
    } else if (which == 1) {
        for (int i = tid; i < n; i += 1024) {
            float wv = w[i];
            float tv = (fabsf(wv) > delta) ? (wv > 0.f ? 1.f : -1.f) : 0.0f;
            int r = i % 9; int t = i / 9; int ic = t % 32; int oc = t / 32;
            g_w2h[(r * 32 + ic) * 72 + oc] = __float2half(tv);
        }
    } else if (which == 2) {
        for (int i = tid; i < n; i += 1024) {
            float wv = w[i];
            float tv = (fabsf(wv) > delta) ? (wv > 0.f ? 1.f : -1.f) : 0.0f;
            int r = i % 9; int t = i / 9; int ic = t % 64; int oc = t / 64;
            g_w3h[(r * 64 + ic) * 136 + oc] = __float2half(tv);
        }
    } else {
        for (int i = tid; i < n; i += 1024) {
            float wv = w[i];
            g_qwl[i] = (fabsf(wv) > delta) ? copysignf(alpha, wv) : 0.0f;
        }
        for (int i = tid; i < 64 * 128; i += 1024) g_pool[i] = 0.f;  // zero pool accum
    }
}

// ---------------- conv1: [64,3,224,224] -> h1 NHWC fp16, s2 p1, BN+ReLU ----------------
__global__ __launch_bounds__(256) void conv1_kernel(
    const float* __restrict__ x, const float* __restrict__ g, const float* __restrict__ b,
    const float* __restrict__ m, const float* __restrict__ v) {
    __shared__ __align__(16) float sX[3 * 33 * 33];
    __shared__ __align__(16) float sW[9 * 3 * 32];
    __shared__ float sBNi[32], sBNa[32];

    int tid = threadIdx.x;
    int n = blockIdx.z;
    int ty0 = blockIdx.y * 16, tx0 = blockIdx.x * 16;
    int iy0 = 2 * ty0 - 1, ix0 = 2 * tx0 - 1;

    for (int i = tid; i < 3 * 33 * 33; i += 256) {
        int lx = i % 33; int t = i / 33; int ly = t % 33; int ic = t / 33;
        int gy = iy0 + ly, gx = ix0 + lx;
        float val = 0.f;
        if (gy >= 0 && gy < 224 && gx >= 0 && gx < 224)
            val = x[((n * 3 + ic) * 224 + gy) * 224 + gx];
        sX[i] = val;
    }
    for (int i = tid; i < 9 * 3 * 32; i += 256) sW[i] = g_w1r[i];
    if (tid < 32) {
        float inv = g[tid] / sqrtf(v[tid] + EPSBN);
        sBNi[tid] = inv; sBNa[tid] = b[tid] - m[tid] * inv;
    }
    __syncthreads();

    int py = tid / 16, px = tid % 16;
    float acc[32];
#pragma unroll
    for (int k = 0; k < 32; ++k) acc[k] = 0.f;

    for (int ic = 0; ic < 3; ++ic) {
#pragma unroll
        for (int r = 0; r < 9; ++r) {
            float xv = sX[ic * 1089 + (2 * py + r / 3) * 33 + (2 * px + r % 3)];
            const float4* w4 = (const float4*)&sW[(r * 3 + ic) * 32];
#pragma unroll
            for (int j = 0; j < 8; ++j) {
                float4 w = w4[j];
                acc[4 * j + 0] += xv * w.x;
                acc[4 * j + 1] += xv * w.y;
                acc[4 * j + 2] += xv * w.z;
                acc[4 * j + 3] += xv * w.w;
            }
        }
    }

    int oy = ty0 + py, ox = tx0 + px;
    long pix = ((long)(n * 112 + oy)) * 112 + ox;
    unsigned short buf[32];
#pragma unroll
    for (int oc = 0; oc < 32; ++oc) {
        float val = fmaxf(acc[oc] * sBNi[oc] + sBNa[oc], 0.f);
        __half h = __float2half(val);
        buf[oc] = *reinterpret_cast<unsigned short*>(&h);
    }
    uint4* dst = (uint4*)(g_h1 + pix * 32);
    const uint4* srcb = (const uint4*)buf;
#pragma unroll
    for (int j = 0; j < 4; ++j) dst[j] = srcb[j];
}

// ---------------- conv2 (tensor core): h1 -> h2, 3x3 s1 p1, BN+ReLU ----------------
// Block 8x16 px (M=128), N=64 oc, 8 warps (4 m x 2 n). K = 9 taps x 32 ch.
// Epilogue staged through smem -> fully coalesced uint4 stores.
__global__ __launch_bounds__(256, 3) void conv2_mma(
    const float* __restrict__ g, const float* __restrict__ b,
    const float* __restrict__ m, const float* __restrict__ v) {
    extern __shared__ __align__(16) char smem[];
    __half* sX = (__half*)smem;                  // 180 rows x 40 ch (80B rows)
    __half* sW = (__half*)(smem + 14400);        // 288 rows x 72 (144B rows)
    __half* sOut = (__half*)smem;                // epilogue: 128 px x 72 ch (144B rows), 18432 B
    __shared__ float sSc[64], sAd[64];

    int tid = threadIdx.x;
    int n = blockIdx.z;
    int ty0 = blockIdx.y * 8, tx0 = blockIdx.x * 16;

    {   // weights: 41472 B = 2592 uint4
        const uint4* wsrc = (const uint4*)g_w2h;
        uint4* wdst = (uint4*)sW;
        for (int i = tid; i < 2592; i += 256) wdst[i] = wsrc[i];
    }
    {   // activations: 180 px x 4 segs of 16B (32 ch fp16 = 64 B/pixel)
        for (int i = tid; i < 720; i += 256) {
            int r = i >> 2, s = i & 3;
            int ly = r / 18, lx = r % 18;
            int gy = ty0 - 1 + ly, gx = tx0 - 1 + lx;
            uint4 val = make_uint4(0, 0, 0, 0);
            if (gy >= 0 && gy < 112 && gx >= 0 && gx < 112) {
                long pix = ((long)(n * 112 + gy)) * 112 + gx;
                val = *(const uint4*)(g_h1 + pix * 32 + s * 8);
            }
            *(uint4*)(sX + r * 40 + s * 8) = val;
        }
    }
    if (tid < 64) {
        float inv = g[tid] / sqrtf(v[tid] + EPSBN);
        sSc[tid] = g_alpha[1] * inv;
        sAd[tid] = b[tid] - m[tid] * inv;
    }
    __syncthreads();

    int warp = tid >> 5, lane = tid & 31;
    int wm = warp & 3, wn = warp >> 2;
    int prow = lane & 15, khalf = lane >> 4;

    unsigned sXu = sptr(sX), sWu = sptr(sW);
    unsigned aB0 = sXu + (((wm * 2 + 0) * 18 + prow) * 40 + khalf * 8) * 2;
    unsigned aB1 = sXu + (((wm * 2 + 1) * 18 + prow) * 40 + khalf * 8) * 2;
    unsigned bOff = (unsigned)(prow * 72 + wn * 32 + khalf * 8) * 2;

    float d[2][4][4];
#pragma unroll
    for (int i = 0; i < 2; ++i)
#pragma unroll
        for (int j = 0; j < 4; ++j)
#pragma unroll
            for (int k = 0; k < 4; ++k) d[i][j][k] = 0.f;

#pragma unroll
    for (int t = 0; t < 9; ++t) {
        unsigned toff = (unsigned)((t / 3) * 18 + (t % 3)) * 80;
#pragma unroll
        for (int kk = 0; kk < 2; ++kk) {
            unsigned wrow = sWu + (unsigned)(t * 32 + kk * 16) * 144 + bOff;
            unsigned b0, b1, b2, b3, b4, b5, b6, b7;
            ldsm4t(b0, b1, b2, b3, wrow);
            ldsm4t(b4, b5, b6, b7, wrow + 32);
            unsigned a0, a1, a2, a3;
            ldsm4(a0, a1, a2, a3, aB0 + toff + kk * 32);
            mma_f16(d[0][0], a0, a1, a2, a3, b0, b1);
            mma_f16(d[0][1], a0, a1, a2, a3, b2, b3);
            mma_f16(d[0][2], a0, a1, a2, a3, b4, b5);
            mma_f16(d[0][3], a0, a1, a2, a3, b6, b7);
            ldsm4(a0, a1, a2, a3, aB1 + toff + kk * 32);
            mma_f16(d[1][0], a0, a1, a2, a3, b0, b1);
            mma_f16(d[1][1], a0, a1, a2, a3, b2, b3);
            mma_f16(d[1][2], a0, a1, a2, a3, b4, b5);
            mma_f16(d[1][3], a0, a1, a2, a3, b6, b7);
        }
    }

    // epilogue: BN+ReLU into smem staging (conflict-free), then coalesced stores
    __syncthreads();   // everyone done reading sX/sW before overlay
#pragma unroll
    for (int i = 0; i < 2; ++i) {
#pragma unroll
        for (int nt = 0; nt < 4; ++nt) {
            int oc = wn * 32 + nt * 8 + 2 * (lane & 3);
            float sc0 = sSc[oc], ad0 = sAd[oc];
            float sc1 = sSc[oc + 1], ad1 = sAd[oc + 1];
#pragma unroll
            for (int rr = 0; rr < 2; ++rr) {
                int p = wm * 32 + i * 16 + (lane >> 2) + rr * 8;
                float v0 = fmaxf(d[i][nt][rr * 2 + 0] * sc0 + ad0, 0.f);
                float v1 = fmaxf(d[i][nt][rr * 2 + 1] * sc1 + ad1, 0.f);
                *(unsigned*)(sOut + p * 72 + oc) = pack_half2(v0, v1);
            }
        }
    }
    __syncthreads();
    // 128 px x 8 segs of 16B = 1024 uint4, coalesced: consecutive i -> consecutive 16B
    for (int i = tid; i < 1024; i += 256) {
        int p = i >> 3, s = i & 7;
        int oy = ty0 + (p >> 4), ox = tx0 + (p & 15);
        long pix = ((long)(n * 112 + oy)) * 112 + ox;
        *(uint4*)(g_h2 + pix * 64 + s * 8) = *(const uint4*)(sOut + p * 72 + s * 8);
    }
}

// ---------------- conv3 (tensor core): h2 -> BN+ReLU -> global-avg-pool (fused) ----------------
// Block 8x8 px (M=64), N=128 oc, 8 warps (2 m x 4 n). 3x3 s2 p1.
// Input tile stored as 4 parity planes (9x9 each) -> conflict-free A ldsm.
// Single weight buffer + register-staged prefetch -> 64 KB smem -> 3 CTAs/SM.
__global__ __launch_bounds__(256, 3) void conv3_mma(
    const float* __restrict__ g, const float* __restrict__ b,
    const float* __restrict__ m, const float* __restrict__ v) {
    extern __shared__ __align__(16) char smem[];
    __half* sX = (__half*)smem;                  // 4 planes x 81 rows x 72 ch = 46656 B
    uint4* sW = (uint4*)(smem + 46656);          // 1088 uint4 = 17408 B (one tap)
    __shared__ float sSc[128], sAd[128];

    int tid = threadIdx.x;
    int n = blockIdx.z;
    int ty0 = blockIdx.y * 8, tx0 = blockIdx.x * 8;
    int iy0 = 2 * ty0 - 1, ix0 = 2 * tx0 - 1;

    // activations into parity planes: 4*81 px x 8 segs of 16B = 2592 uint4
    for (int i = tid; i < 2592; i += 256) {
        int px_i = i >> 3, s = i & 7;
        int plane = px_i / 81, rr = px_i % 81;
        int ly = rr / 9, lx = rr % 9;
        int ey = plane >> 1, ex = plane & 1;
        int gy = iy0 + 2 * ly + ey, gx = ix0 + 2 * lx + ex;
        uint4 val = make_uint4(0, 0, 0, 0);
        if (gy >= 0 && gy < 112 && gx >= 0 && gx < 112) {
            long pix = ((long)(n * 112 + gy)) * 112 + gx;
            val = *(const uint4*)(g_h2 + pix * 64 + s * 8);
        }
        *(uint4*)(sX + (plane * 81 + rr) * 72 + s * 8) = val;
    }
    if (tid < 128) {
        float inv = g[tid] / sqrtf(v[tid] + EPSBN);
        sSc[tid] = g_alpha[2] * inv;
        sAd[tid] = b[tid] - m[tid] * inv;
    }

    // reg-stage tap 0 and store to smem
    const uint4* wglob = (const uint4*)g_w3h;    // tap t at offset t*1088
    uint4 wreg[5];
#pragma unroll
    for (int k = 0; k < 5; ++k) {
        int i = tid + k * 256;
        wreg[k] = (i < 1088) ? wglob[i] : make_uint4(0, 0, 0, 0);
    }
#pragma unroll
    for (int k = 0; k < 5; ++k) {
        int i = tid + k * 256;
        if (i < 1088) sW[i] = wreg[k];
    }
    __syncthreads();

    int warp = tid >> 5, lane = tid & 31;
    int wm = warp & 1, wn = warp >> 1;
    int prow = lane & 15, khalf = lane >> 4;
    int p0 = wm * 32 + prow, p1 = p0 + 16;
    int ppy0 = p0 >> 3, ppx0 = p0 & 7;
    int ppy1 = p1 >> 3, ppx1 = p1 & 7;

    unsigned sXu = sptr(sX);
    unsigned sWu = sptr(sW);
    // per-thread invariant parts of A addresses (tap adds a compile-time constant)
    unsigned aInv0 = sXu + ((unsigned)(ppy0 * 9 + ppx0) * 72 + khalf * 8) * 2;
    unsigned aInv1 = sXu + ((unsigned)(ppy1 * 9 + ppx1) * 72 + khalf * 8) * 2;
    unsigned bOff = sWu + (unsigned)(prow * 136 + wn * 32 + khalf * 8) * 2;

    float d[2][4][4];
#pragma unroll
    for (int i = 0; i < 2; ++i)
#pragma unroll
        for (int j = 0; j < 4; ++j)
#pragma unroll
            for (int k = 0; k < 4; ++k) d[i][j][k] = 0.f;

#pragma unroll
    for (int t = 0; t < 9; ++t) {
        // prefetch next tap's weights into registers (overlaps with MMA below)
        if (t < 8) {
            const uint4* src = wglob + (t + 1) * 1088;
#pragma unroll
            for (int k = 0; k < 5; ++k) {
                int i = tid + k * 256;
                if (i < 1088) wreg[k] = src[i];
            }
        }
        const int dy = t / 3, dx = t % 3;                 // compile-time (unrolled)
        const int plane = (dy & 1) * 2 + (dx & 1);
        const int oy = dy >> 1, ox = dx >> 1;
        const unsigned tapOff = (unsigned)((plane * 81 + oy * 9 + ox) * 72) * 2;
        unsigned aA0 = aInv0 + tapOff;
        unsigned aA1 = aInv1 + tapOff;
#pragma unroll
        for (int kk = 0; kk < 4; ++kk) {
            unsigned wrow = bOff + (unsigned)kk * (16 * 272);
            unsigned b0, b1, b2, b3, b4, b5, b6, b7;
            ldsm4t(b0, b1, b2, b3, wrow);
            ldsm4t(b4, b5, b6, b7, wrow + 32);
            unsigned a0, a1, a2, a3;
            ldsm4(a0, a1, a2, a3, aA0 + kk * 32);
            mma_f16(d[0][0], a0, a1, a2, a3, b0, b1);
            mma_f16(d[0][1], a0, a1, a2, a3, b2, b3);
            mma_f16(d[0][2], a0, a1, a2, a3, b4, b5);
            mma_f16(d[0][3], a0, a1, a2, a3, b6, b7);
            ldsm4(a0, a1, a2, a3, aA1 + kk * 32);
            mma_f16(d[1][0], a0, a1, a2, a3, b0, b1);
            mma_f16(d[1][1], a0, a1, a2, a3, b2, b3);
            mma_f16(d[1][2], a0, a1, a2, a3, b4, b5);
            mma_f16(d[1][3], a0, a1, a2, a3, b6, b7);
        }
        __syncthreads();                       // all warps done reading sW for tap t
        if (t < 8) {
#pragma unroll
            for (int k = 0; k < 5; ++k) {
                int i = tid + k * 256;
                if (i < 1088) sW[i] = wreg[k];
            }
        }
        __syncthreads();                       // sW holds tap t+1
    }

    // epilogue: BN+ReLU, sum over this block's 64 pixels, atomicAdd into pool
#pragma unroll
    for (int nt = 0; nt < 4; ++nt) {
        int oc = wn * 32 + nt * 8 + 2 * (lane & 3);
        float sc0 = sSc[oc], ad0 = sAd[oc];
        float sc1 = sSc[oc + 1], ad1 = sAd[oc + 1];
        float s0 = 0.f, s1 = 0.f;
#pragma unroll
        for (int i = 0; i < 2; ++i) {
            s0 += fmaxf(d[i][nt][0] * sc0 + ad0, 0.f) + fmaxf(d[i][nt][2] * sc0 + ad0, 0.f);
            s1 += fmaxf(d[i][nt][1] * sc1 + ad1, 0.f) + fmaxf(d[i][nt][3] * sc1 + ad1, 0.f);
        }
#pragma unroll
        for (int off = 4; off < 32; off <<= 1) {
            s0 += __shfl_xor_sync(0xffffffff, s0, off);
            s1 += __shfl_xor_sync(0xffffffff, s1, off);
        }
        if (lane < 4) {
            atomicAdd(&g_pool[n * 128 + oc], s0);
            atomicAdd(&g_pool[n * 128 + oc + 1], s1);
        }
    }
}

// ---------------- final linear: out[n,c] = (pool/3136) @ qwl.T + bl ----------------
__global__ void final_kernel(const float* __restrict__ bl, float* __restrict__ out) {
    int tid = blockIdx.x * blockDim.x + threadIdx.x;
    if (tid >= 640) return;
    int n = tid / 10, c = tid % 10;
    const float* p = g_pool + n * 128;
    const float* w = g_qwl + c * 128;
    float s = 0.f;
#pragma unroll 8
    for (int k = 0; k < 128; ++k) s += p[k] * w[k];
    out[tid] = s * (1.0f / 3136.0f) + bl[c];
}

// ---------------- launch ----------------
extern "C" void kernel_launch(void* const* d_in, const int* in_sizes, int n_in,
                              void* d_out, int out_size) {
    const float* x  = (const float*)d_in[0];
    const float* w1 = (const float*)d_in[1];
    const float* g1 = (const float*)d_in[2];
    const float* b1 = (const float*)d_in[3];
    const float* m1 = (const float*)d_in[4];
    const float* v1 = (const float*)d_in[5];
    const float* w2 = (const float*)d_in[6];
    const float* g2 = (const float*)d_in[7];
    const float* b2 = (const float*)d_in[8];
    const float* m2 = (const float*)d_in[9];
    const float* v2 = (const float*)d_in[10];
    const float* w3 = (const float*)d_in[11];
    const float* g3 = (const float*)d_in[12];
    const float* b3 = (const float*)d_in[13];
    const float* m3 = (const float*)d_in[14];
    const float* v3 = (const float*)d_in[15];
    const float* wl = (const float*)d_in[16];
    const float* bl = (const float*)d_in[17];
    float* out = (float*)d_out;

    cudaFuncSetAttribute((const void*)conv2_mma,
                         cudaFuncAttributeMaxDynamicSharedMemorySize, 55872);
    cudaFuncSetAttribute((const void*)conv3_mma,
                         cudaFuncAttributeMaxDynamicSharedMemorySize, 64064);

    prep_kernel<<<4, 1024>>>(w1, w2, w3, wl);
    conv1_kernel<<<dim3(7, 7, 64), 256>>>(x, g1, b1, m1, v1);
    conv2_mma<<<dim3(7, 14, 64), 256, 55872>>>(g2, b2, m2, v2);
    conv3_mma<<<dim3(7, 7, 64), 256, 64064>>>(g3, b3, m3, v3);
    final_kernel<<<3, 256>>>(bl, out);
}